// round 4
// baseline (speedup 1.0000x reference)
#include <cuda_runtime.h>
#include <cuda_bf16.h>
#include <math.h>
#include <stdint.h>

#define S_    1024
#define EMB_  1024
#define M_    6
#define A_    4
#define QH_   2
#define D_    128
#define E_    (S_*A_)

typedef __nv_bfloat16 bf16;

// ---------------- scratch ----------------
__device__ float g_yq[S_*M_*QH_*D_];
__device__ float g_yk[S_*M_*D_];
__device__ float g_yv[S_*M_*D_];
__device__ float g_probs[S_*M_];
__device__ float g_ent[S_];
__device__ int   g_primary[S_];
__device__ int   g_kvidx[E_];
__device__ float g_kvw[E_];
__device__ int   g_rank[E_];
__device__ int   g_list[M_*E_];
__device__ int   g_counts[M_];
// pre-converted bf16 hi/lo operands
__device__ bf16  g_xh[S_*EMB_],       g_xl[S_*EMB_];
__device__ bf16  g_wqh[1536*EMB_],    g_wql[1536*EMB_];
__device__ bf16  g_wkh[768*EMB_],     g_wkl[768*EMB_];
__device__ bf16  g_wvh[768*EMB_],     g_wvl[768*EMB_];
__device__ bf16  g_woh[EMB_*EMB_],    g_wol[EMB_*EMB_];
__device__ bf16  g_qh[M_*E_*QH_*D_],  g_ql[M_*E_*QH_*D_];
__device__ bf16  g_kh[M_*E_*D_],      g_kl[M_*E_*D_];
__device__ bf16  g_vth[M_*D_*E_],     g_vtl[M_*D_*E_];   // V transposed [m][d][rank]
__device__ bf16  g_aoh[S_*A_*QH_*D_], g_aol[S_*A_*QH_*D_];
__device__ float g_part[2*S_*EMB_];

// ---------------- helpers ----------------
__device__ __forceinline__ uint32_t smem_u32(const void* p) {
    return (uint32_t)__cvta_generic_to_shared(p);
}
__device__ __forceinline__ void ldsm4(uint32_t* r, const void* p) {
    uint32_t a = smem_u32(p);
    asm volatile("ldmatrix.sync.aligned.m8n8.x4.shared.b16 {%0,%1,%2,%3}, [%4];"
                 : "=r"(r[0]), "=r"(r[1]), "=r"(r[2]), "=r"(r[3]) : "r"(a));
}
__device__ __forceinline__ void mma16816(float* c, const uint32_t* a, uint32_t b0, uint32_t b1) {
    asm volatile("mma.sync.aligned.m16n8k16.row.col.f32.bf16.bf16.f32 "
                 "{%0,%1,%2,%3}, {%4,%5,%6,%7}, {%8,%9}, {%0,%1,%2,%3};"
                 : "+f"(c[0]), "+f"(c[1]), "+f"(c[2]), "+f"(c[3])
                 : "r"(a[0]), "r"(a[1]), "r"(a[2]), "r"(a[3]), "r"(b0), "r"(b1));
}
__device__ __forceinline__ void cvt4(float4 v, uint2& hi, uint2& lo) {
    bf16 h0 = __float2bfloat16(v.x), h1 = __float2bfloat16(v.y);
    bf16 h2 = __float2bfloat16(v.z), h3 = __float2bfloat16(v.w);
    bf16 l0 = __float2bfloat16(v.x - __bfloat162float(h0));
    bf16 l1 = __float2bfloat16(v.y - __bfloat162float(h1));
    bf16 l2 = __float2bfloat16(v.z - __bfloat162float(h2));
    bf16 l3 = __float2bfloat16(v.w - __bfloat162float(h3));
    __nv_bfloat162 H0, H1, L0, L1;
    H0.x = h0; H0.y = h1; H1.x = h2; H1.y = h3;
    L0.x = l0; L0.y = l1; L1.x = l2; L1.y = l3;
    hi.x = *(uint32_t*)&H0; hi.y = *(uint32_t*)&H1;
    lo.x = *(uint32_t*)&L0; lo.y = *(uint32_t*)&L1;
}
__device__ __forceinline__ void packhl(float x, float y, uint32_t& hi, uint32_t& lo) {
    __nv_bfloat162 H, L;
    H.x = __float2bfloat16(x); H.y = __float2bfloat16(y);
    L.x = __float2bfloat16(x - __bfloat162float(H.x));
    L.y = __float2bfloat16(y - __bfloat162float(H.y));
    hi = *(uint32_t*)&H; lo = *(uint32_t*)&L;
}
__device__ __forceinline__ void splitf(float v, bf16& h, bf16& l) {
    h = __float2bfloat16(v);
    l = __float2bfloat16(v - __bfloat162float(h));
}

// ---------------- one-shot hi/lo conversion of x + all weights ----------------
// segments (in float4 units): x 262144 | wq 393216 | wk 196608 | wv 196608 | wo 262144
__global__ void cvt_all_kernel(const float* __restrict__ x,  const float* __restrict__ wq,
                               const float* __restrict__ wk, const float* __restrict__ wv,
                               const float* __restrict__ wo) {
    int i = blockIdx.x * 256 + threadIdx.x;
    const float* src; bf16 *dh, *dl; int off;
    if (i < 262144)        { src = x;  dh = g_xh;  dl = g_xl;  off = i; }
    else if (i < 655360)   { src = wq; dh = g_wqh; dl = g_wql; off = i - 262144; }
    else if (i < 851968)   { src = wk; dh = g_wkh; dl = g_wkl; off = i - 655360; }
    else if (i < 1048576)  { src = wv; dh = g_wvh; dl = g_wvl; off = i - 851968; }
    else                   { src = wo; dh = g_woh; dl = g_wol; off = i - 1048576; }
    float4 v = ((const float4*)src)[off];
    uint2 h, l;
    cvt4(v, h, l);
    ((uint2*)dh)[off] = h;
    ((uint2*)dl)[off] = l;
}

// ---------------- router ----------------
__global__ void router_kernel(const float* __restrict__ x, const float* __restrict__ wr) {
    int gw   = (blockIdx.x * blockDim.x + threadIdx.x) >> 5;
    int lane = threadIdx.x & 31;
    if (gw >= S_) return;
    const float* xr = x + gw * EMB_;
    float acc[M_];
#pragma unroll
    for (int m = 0; m < M_; m++) acc[m] = 0.f;
    for (int i = lane; i < EMB_; i += 32) {
        float xv = xr[i];
#pragma unroll
        for (int m = 0; m < M_; m++) acc[m] += xv * wr[m*EMB_ + i];
    }
#pragma unroll
    for (int m = 0; m < M_; m++)
        for (int o = 16; o; o >>= 1) acc[m] += __shfl_xor_sync(0xffffffffu, acc[m], o);
    if (lane == 0) {
        float mx = acc[0];
#pragma unroll
        for (int m = 1; m < M_; m++) mx = fmaxf(mx, acc[m]);
        float ex[M_], ssum = 0.f;
#pragma unroll
        for (int m = 0; m < M_; m++) { ex[m] = expf(acc[m] - mx); ssum += ex[m]; }
        float inv = 1.f / ssum;
        float ent = 0.f;
#pragma unroll
        for (int m = 0; m < M_; m++) {
            float p = ex[m] * inv;
            g_probs[gw*M_ + m] = p;
            ent -= p * logf(p + 1e-8f);
        }
        g_ent[gw] = ent;
        float v[M_];
#pragma unroll
        for (int m = 0; m < M_; m++) v[m] = acc[m];
        int   idx[A_]; float tv[A_];
#pragma unroll
        for (int a = 0; a < A_; a++) {
            float best = -INFINITY; int bi = 0;
#pragma unroll
            for (int m = 0; m < M_; m++) if (v[m] > best) { best = v[m]; bi = m; }
            idx[a] = bi; tv[a] = best; v[bi] = -INFINITY;
        }
        float wv[A_], ws = 0.f;
#pragma unroll
        for (int a = 0; a < A_; a++) { wv[a] = expf(tv[a] - tv[0]); ws += wv[a]; }
        float winv = 1.f / ws;
#pragma unroll
        for (int a = 0; a < A_; a++) {
            g_kvidx[gw*A_ + a] = idx[a];
            g_kvw  [gw*A_ + a] = wv[a] * winv;
        }
        g_primary[gw] = idx[0];
    }
}

// ---------------- per-expert lists + ranks ----------------
__global__ void build_lists_kernel() {
    int m    = threadIdx.x >> 5;
    int lane = threadIdx.x & 31;
    if (m >= M_) return;
    int base = 0;
    for (int e0 = 0; e0 < E_; e0 += 32) {
        int e = e0 + lane;
        int gidx = g_kvidx[e];
        unsigned mask = __ballot_sync(0xffffffffu, gidx == m);
        if (gidx == m) {
            int r = base + __popc(mask & ((1u << lane) - 1u));
            g_rank[e] = r;
            g_list[m*E_ + r] = e;
        }
        base += __popc(mask);
    }
    if (lane == 0) g_counts[m] = base;
}

// ---------------- aux loss ----------------
__global__ void aux_reduce_kernel(float* __restrict__ d_out, int out_size) {
    __shared__ float red[256];
    __shared__ float tot[13];
    int tid = threadIdx.x;
    float pf[M_], pp[M_], pe = 0.f;
#pragma unroll
    for (int m = 0; m < M_; m++) { pf[m] = 0.f; pp[m] = 0.f; }
    for (int t = tid; t < S_; t += 256) {
        int pm = g_primary[t];
        pe += g_ent[t];
#pragma unroll
        for (int m = 0; m < M_; m++) {
            pp[m] += g_probs[t*M_ + m];
            pf[m] += (pm == m) ? 1.f : 0.f;
        }
    }
    for (int q = 0; q < 13; q++) {
        float v = (q < 6) ? pf[q] : (q < 12 ? pp[q-6] : pe);
        red[tid] = v; __syncthreads();
        for (int s = 128; s > 0; s >>= 1) {
            if (tid < s) red[tid] += red[tid + s];
            __syncthreads();
        }
        if (tid == 0) tot[q] = red[0];
        __syncthreads();
    }
    if (tid == 0) {
        float bal = 0.f;
#pragma unroll
        for (int m = 0; m < M_; m++) bal += (tot[m] / (float)S_) * (tot[6+m] / (float)S_);
        bal *= (float)M_;
        float aux = 0.01f * bal - 0.01f * (tot[12] / (float)S_);
        d_out[out_size - 1] = aux;
    }
}

// ---------------- GEMM: bf16 hi/lo inputs, double-buffered, 3-seg, split-K ----------------
__global__ __launch_bounds__(256) void gemm3seg(
    const bf16* __restrict__ Ah, const bf16* __restrict__ Al,
    const bf16* __restrict__ B0h, const bf16* __restrict__ B0l,
    const bf16* __restrict__ B1h, const bf16* __restrict__ B1l,
    const bf16* __restrict__ B2h, const bf16* __restrict__ B2l,
    float* __restrict__ C0, float* __restrict__ C1, float* __restrict__ C2,
    int K, int nb0, int nb1, int N0, int N1, int N2)
{
    extern __shared__ bf16 ds[];
    const int ST = 4*128*40;
    int tid = threadIdx.x, lane = tid & 31, warp = tid >> 5;
    int wm = warp >> 1, wn = warp & 1;

    int Klen = K / gridDim.z;
    int kOff = blockIdx.z * Klen;

    const bf16 *Bph, *Bpl; float* Cp; int N; int bxl = blockIdx.x;
    if (bxl < nb0)             { Bph = B0h; Bpl = B0l; Cp = C0; N = N0; }
    else if (bxl < nb0 + nb1)  { Bph = B1h; Bpl = B1l; Cp = C1; N = N1; bxl -= nb0; }
    else                       { Bph = B2h; Bpl = B2l; Cp = C2; N = N2; bxl -= nb0 + nb1; }
    Cp += (size_t)blockIdx.z * S_ * N;

    int arow = tid >> 1;
    int kq   = (tid & 1) * 16;
    size_t aoff = (size_t)(blockIdx.y * 128 + arow) * K + kOff + kq;
    size_t boff = (size_t)(bxl       * 128 + arow) * K + kOff + kq;

    float acc[2][8][4];
#pragma unroll
    for (int mt = 0; mt < 2; mt++)
#pragma unroll
        for (int nt = 0; nt < 8; nt++)
#pragma unroll
            for (int c = 0; c < 4; c++) acc[mt][nt][c] = 0.f;

    int g   = lane >> 3;
    int lr  = (lane & 7) + ((g & 1) << 3);
    int lcA = (g >> 1) << 3;
    int brn = (lane & 7) + ((g >> 1) << 3);
    int lcB = (g & 1) << 3;

    // stage 0 fill
    {
        bf16* Ahi = ds; bf16* Alo = ds + 128*40;
        bf16* Bhi = ds + 2*128*40; bf16* Blo = ds + 3*128*40;
#pragma unroll
        for (int j = 0; j < 4; j++) {
            int kk = kq + 4*j;
            *(uint2*)&Ahi[arow*40 + kk] = *(const uint2*)(Ah + aoff + 4*j);
            *(uint2*)&Alo[arow*40 + kk] = *(const uint2*)(Al + aoff + 4*j);
            *(uint2*)&Bhi[arow*40 + kk] = *(const uint2*)(Bph + boff + 4*j);
            *(uint2*)&Blo[arow*40 + kk] = *(const uint2*)(Bpl + boff + 4*j);
        }
    }
    __syncthreads();

    for (int kt = 0; kt < Klen; kt += 32) {
        int cur = (kt >> 5) & 1;
        bool more = (kt + 32) < Klen;
        uint2 ra[4], rb[4], rc[4], rd[4];
        if (more) {
#pragma unroll
            for (int j = 0; j < 4; j++) {
                ra[j] = *(const uint2*)(Ah  + aoff + kt + 32 + 4*j);
                rb[j] = *(const uint2*)(Al  + aoff + kt + 32 + 4*j);
                rc[j] = *(const uint2*)(Bph + boff + kt + 32 + 4*j);
                rd[j] = *(const uint2*)(Bpl + boff + kt + 32 + 4*j);
            }
        }
        const bf16* Ahi = ds + cur*ST;
        const bf16* Alo = Ahi + 128*40;
        const bf16* Bhi = Ahi + 2*128*40;
        const bf16* Blo = Ahi + 3*128*40;
#pragma unroll
        for (int kh = 0; kh < 2; kh++) {
            uint32_t ah[2][4], al[2][4], bh[4][4], bl[4][4];
#pragma unroll
            for (int mt = 0; mt < 2; mt++) {
                int r = wm*32 + mt*16 + lr;
                int c = kh*16 + lcA;
                ldsm4(ah[mt], &Ahi[r*40 + c]);
                ldsm4(al[mt], &Alo[r*40 + c]);
            }
#pragma unroll
            for (int j = 0; j < 4; j++) {
                int r = wn*64 + j*16 + brn;
                int c = kh*16 + lcB;
                ldsm4(bh[j], &Bhi[r*40 + c]);
                ldsm4(bl[j], &Blo[r*40 + c]);
            }
            // pass 1: hi*hi (16 independent mmas)
#pragma unroll
            for (int mt = 0; mt < 2; mt++)
#pragma unroll
                for (int nt = 0; nt < 8; nt++)
                    mma16816(acc[mt][nt], ah[mt], bh[nt>>1][(nt&1)*2], bh[nt>>1][(nt&1)*2+1]);
            // pass 2: hi*lo
#pragma unroll
            for (int mt = 0; mt < 2; mt++)
#pragma unroll
                for (int nt = 0; nt < 8; nt++)
                    mma16816(acc[mt][nt], ah[mt], bl[nt>>1][(nt&1)*2], bl[nt>>1][(nt&1)*2+1]);
            // pass 3: lo*hi
#pragma unroll
            for (int mt = 0; mt < 2; mt++)
#pragma unroll
                for (int nt = 0; nt < 8; nt++)
                    mma16816(acc[mt][nt], al[mt], bh[nt>>1][(nt&1)*2], bh[nt>>1][(nt&1)*2+1]);
        }
        if (more) {
            bf16* Ahi2 = ds + (cur^1)*ST;
            bf16* Alo2 = Ahi2 + 128*40;
            bf16* Bhi2 = Ahi2 + 2*128*40;
            bf16* Blo2 = Ahi2 + 3*128*40;
#pragma unroll
            for (int j = 0; j < 4; j++) {
                int kk = kq + 4*j;
                *(uint2*)&Ahi2[arow*40 + kk] = ra[j];
                *(uint2*)&Alo2[arow*40 + kk] = rb[j];
                *(uint2*)&Bhi2[arow*40 + kk] = rc[j];
                *(uint2*)&Blo2[arow*40 + kk] = rd[j];
            }
        }
        __syncthreads();
    }

    int crow0 = blockIdx.y*128 + wm*32 + (lane >> 2);
    int ccol0 = bxl*128 + wn*64 + (lane & 3)*2;
#pragma unroll
    for (int mt = 0; mt < 2; mt++)
#pragma unroll
        for (int nt = 0; nt < 8; nt++) {
            float* p = Cp + (size_t)(crow0 + mt*16) * N + ccol0 + nt*8;
            *(float2*)p           = make_float2(acc[mt][nt][0], acc[mt][nt][1]);
            *(float2*)(p + 8*N)   = make_float2(acc[mt][nt][2], acc[mt][nt][3]);
        }
}

// ---------------- sum split-K partials ----------------
__global__ void add_out_kernel(float* __restrict__ out) {
    int i = blockIdx.x * 256 + threadIdx.x;
    out[i] = g_part[i] + g_part[i + S_*EMB_];
}

// ---------------- gather + RoPE -> bf16 hi/lo; Q pre-scaled; V transposed ----------------
__global__ void gather_rope_kernel() {
    int e = blockIdx.x;
    int d = threadIdx.x;
    int m = g_kvidx[e];
    int r = g_rank[e];
    int t = e >> 2;
    int dm = d & 63;
    float invf = expf(-(float)dm * (9.210340371976184f / 64.0f));
    float fr = (float)r * invf;
    float sn, cs;
    sincosf(fr, &sn, &cs);
    int   partner = (d < 64) ? d + 64 : d - 64;
    float sgn     = (d < 64) ? -1.f : 1.f;
    int ro = m * E_ + r;
    const float scale = 0.08838834764831845f;
    const float* kb = g_yk + t * (M_ * D_) + m * D_;
    float kvv = kb[d] * cs + sgn * kb[partner] * sn;
    splitf(kvv, g_kh[ro*D_ + d], g_kl[ro*D_ + d]);
    float vv = g_yv[t*(M_*D_) + m*D_ + d];
    splitf(vv, g_vth[(m*D_ + d)*E_ + r], g_vtl[(m*D_ + d)*E_ + r]);
#pragma unroll
    for (int h = 0; h < QH_; h++) {
        const float* qb = g_yq + t * (M_*QH_*D_) + (m*QH_ + h) * D_;
        float qv = (qb[d] * cs + sgn * qb[partner] * sn) * scale;
        splitf(qv, g_qh[(ro*QH_ + h)*D_ + d], g_ql[(ro*QH_ + h)*D_ + d]);
    }
}

// ---------------- tensor-core flash attention ----------------
#define AQH0 0
#define AQL0 8704
#define AKH0 17408
#define AKL0 26112
#define AVH0 34816
#define AVL0 44032
#define ATTN_SMEM_BYTES (53248*2)

__global__ __launch_bounds__(128) void attn_kernel() {
    int m = blockIdx.z, h = blockIdx.y;
    int L = g_counts[m];
    int q0 = blockIdx.x * 64;
    if (q0 >= L) return;

    extern __shared__ bf16 as[];
    int tid = threadIdx.x, lane = tid & 31, wm = tid >> 5;

    int g   = lane >> 3;
    int lr  = (lane & 7) + ((g & 1) << 3);
    int lcA = (g >> 1) << 3;
    int brn = (lane & 7) + ((g >> 1) << 3);
    int lcB = (g & 1) << 3;
    int cb  = (lane & 3) * 2;

    // Q tile (64 x 128), bf16 hi/lo direct copy
    for (int idx = tid; idx < 64*16; idx += 128) {
        int i = idx >> 4, dq = (idx & 15) * 8;
        size_t go = (((size_t)(m*E_ + q0 + i)*QH_ + h) << 7) + dq;
        *(uint4*)&as[AQH0 + i*136 + dq] = *(const uint4*)(g_qh + go);
        *(uint4*)&as[AQL0 + i*136 + dq] = *(const uint4*)(g_ql + go);
    }

    float Oa[16][4];
#pragma unroll
    for (int nt = 0; nt < 16; nt++)
#pragma unroll
        for (int c = 0; c < 4; c++) Oa[nt][c] = 0.f;
    float mrow[2] = {-INFINITY, -INFINITY};
    float lrow[2] = {0.f, 0.f};

    for (int kt = 0; kt < L; kt += 64) {
        __syncthreads();
        for (int idx = tid; idx < 64*16; idx += 128) {
            int j = idx >> 4, dq = (idx & 15) * 8;
            size_t go = (((size_t)(m*E_ + kt + j)) << 7) + dq;
            *(uint4*)&as[AKH0 + j*136 + dq] = *(const uint4*)(g_kh + go);
            *(uint4*)&as[AKL0 + j*136 + dq] = *(const uint4*)(g_kl + go);
        }
        for (int idx = tid; idx < 128*8; idx += 128) {
            int d = idx >> 3, jq = (idx & 7) * 8;
            size_t go = ((size_t)(m*D_ + d))*E_ + kt + jq;
            *(uint4*)&as[AVH0 + d*72 + jq] = *(const uint4*)(g_vth + go);
            *(uint4*)&as[AVL0 + d*72 + jq] = *(const uint4*)(g_vtl + go);
        }
        __syncthreads();

        // S = Q K^T
        float Sacc[8][4];
#pragma unroll
        for (int nt = 0; nt < 8; nt++)
#pragma unroll
            for (int c = 0; c < 4; c++) Sacc[nt][c] = 0.f;
#pragma unroll
        for (int kc = 0; kc < 8; kc++) {
            uint32_t qh[4], ql[4], bh[4][4], bl[4][4];
            ldsm4(qh, &as[AQH0 + (wm*16 + lr)*136 + kc*16 + lcA]);
            ldsm4(ql, &as[AQL0 + (wm*16 + lr)*136 + kc*16 + lcA]);
#pragma unroll
            for (int nt2 = 0; nt2 < 4; nt2++) {
                ldsm4(bh[nt2], &as[AKH0 + (nt2*16 + brn)*136 + kc*16 + lcB]);
                ldsm4(bl[nt2], &as[AKL0 + (nt2*16 + brn)*136 + kc*16 + lcB]);
            }
#pragma unroll
            for (int nt2 = 0; nt2 < 4; nt2++) {
                mma16816(Sacc[2*nt2],   qh, bh[nt2][0], bh[nt2][1]);
                mma16816(Sacc[2*nt2+1], qh, bh[nt2][2], bh[nt2][3]);
            }
#pragma unroll
            for (int nt2 = 0; nt2 < 4; nt2++) {
                mma16816(Sacc[2*nt2],   qh, bl[nt2][0], bl[nt2][1]);
                mma16816(Sacc[2*nt2+1], qh, bl[nt2][2], bl[nt2][3]);
            }
#pragma unroll
            for (int nt2 = 0; nt2 < 4; nt2++) {
                mma16816(Sacc[2*nt2],   ql, bh[nt2][0], bh[nt2][1]);
                mma16816(Sacc[2*nt2+1], ql, bh[nt2][2], bh[nt2][3]);
            }
        }

        // online softmax
        int lim = L - kt;
#pragma unroll
        for (int nt = 0; nt < 8; nt++) {
            int c0 = nt*8 + cb;
            if (c0     >= lim) { Sacc[nt][0] = -1e30f; Sacc[nt][2] = -1e30f; }
            if (c0 + 1 >= lim) { Sacc[nt][1] = -1e30f; Sacc[nt][3] = -1e30f; }
        }
#pragma unroll
        for (int rr = 0; rr < 2; rr++) {
            float mx = -INFINITY;
#pragma unroll
            for (int nt = 0; nt < 8; nt++)
                mx = fmaxf(mx, fmaxf(Sacc[nt][rr*2], Sacc[nt][rr*2+1]));
            mx = fmaxf(mx, __shfl_xor_sync(0xffffffffu, mx, 1));
            mx = fmaxf(mx, __shfl_xor_sync(0xffffffffu, mx, 2));
            float mn = fmaxf(mrow[rr], mx);
            float corr = __expf(mrow[rr] - mn);
            mrow[rr] = mn;
            float ps = 0.f;
#pragma unroll
            for (int nt = 0; nt < 8; nt++) {
                float p0 = __expf(Sacc[nt][rr*2]   - mn);
                float p1 = __expf(Sacc[nt][rr*2+1] - mn);
                Sacc[nt][rr*2] = p0; Sacc[nt][rr*2+1] = p1;
                ps += p0 + p1;
            }
            ps += __shfl_xor_sync(0xffffffffu, ps, 1);
            ps += __shfl_xor_sync(0xffffffffu, ps, 2);
            lrow[rr] = lrow[rr] * corr + ps;
#pragma unroll
            for (int nt = 0; nt < 16; nt++) {
                Oa[nt][rr*2]   *= corr;
                Oa[nt][rr*2+1] *= corr;
            }
        }

        // O += P V
#pragma unroll
        for (int kc2 = 0; kc2 < 4; kc2++) {
            uint32_t pah[4], pal[4];
            packhl(Sacc[2*kc2][0],   Sacc[2*kc2][1],   pah[0], pal[0]);
            packhl(Sacc[2*kc2][2],   Sacc[2*kc2][3],   pah[1], pal[1]);
            packhl(Sacc[2*kc2+1][0], Sacc[2*kc2+1][1], pah[2], pal[2]);
            packhl(Sacc[2*kc2+1][2], Sacc[2*kc2+1][3], pah[3], pal[3]);
#pragma unroll
            for (int nt2 = 0; nt2 < 8; nt2++) {
                uint32_t vh[4], vl[4];
                ldsm4(vh, &as[AVH0 + (nt2*16 + brn)*72 + kc2*16 + lcB]);
                ldsm4(vl, &as[AVL0 + (nt2*16 + brn)*72 + kc2*16 + lcB]);
                // interleave the two accumulators: dependency distance 2
                mma16816(Oa[2*nt2],   pah, vh[0], vh[1]);
                mma16816(Oa[2*nt2+1], pah, vh[2], vh[3]);
                mma16816(Oa[2*nt2],   pah, vl[0], vl[1]);
                mma16816(Oa[2*nt2+1], pah, vl[2], vl[3]);
                mma16816(Oa[2*nt2],   pal, vh[0], vh[1]);
                mma16816(Oa[2*nt2+1], pal, vh[2], vh[3]);
            }
        }
    }

    // epilogue: scatter to token order as bf16 hi/lo (feeds out-proj GEMM)
#pragma unroll
    for (int rr = 0; rr < 2; rr++) {
        int row_local = wm*16 + (lane >> 2) + 8*rr;
        int gr = q0 + row_local;
        if (gr < L) {
            int e = g_list[m*E_ + gr];
            int t = e >> 2, a = e & 3;
            float w = g_kvw[t*A_ + a] / lrow[rr];
            size_t base = (size_t)t*(A_*QH_*D_) + (a*QH_ + h)*D_;
#pragma unroll
            for (int nt = 0; nt < 16; nt++) {
                int col = nt*8 + cb;
                uint32_t hi, lo;
                packhl(Oa[nt][rr*2]*w, Oa[nt][rr*2+1]*w, hi, lo);
                *(uint32_t*)(g_aoh + base + col) = hi;
                *(uint32_t*)(g_aol + base + col) = lo;
            }
        }
    }
}

// ---------------- launch ----------------
extern "C" void kernel_launch(void* const* d_in, const int* in_sizes, int n_in,
                              void* d_out, int out_size)
{
    const float* x  = (const float*)d_in[0];
    const float* wq = (const float*)d_in[1];
    const float* wk = (const float*)d_in[2];
    const float* wv = (const float*)d_in[3];
    const float* wr = (const float*)d_in[4];
    const float* wo = (const float*)d_in[5];
    float* out = (float*)d_out;

    float *yq, *yk, *yv, *part;
    bf16 *xh, *xl, *wqh, *wql, *wkh, *wkl, *wvh, *wvl, *woh, *wol, *aoh, *aol;
    cudaGetSymbolAddress((void**)&yq, g_yq);
    cudaGetSymbolAddress((void**)&yk, g_yk);
    cudaGetSymbolAddress((void**)&yv, g_yv);
    cudaGetSymbolAddress((void**)&part, g_part);
    cudaGetSymbolAddress((void**)&xh,  g_xh);  cudaGetSymbolAddress((void**)&xl,  g_xl);
    cudaGetSymbolAddress((void**)&wqh, g_wqh); cudaGetSymbolAddress((void**)&wql, g_wql);
    cudaGetSymbolAddress((void**)&wkh, g_wkh); cudaGetSymbolAddress((void**)&wkl, g_wkl);
    cudaGetSymbolAddress((void**)&wvh, g_wvh); cudaGetSymbolAddress((void**)&wvl, g_wvl);
    cudaGetSymbolAddress((void**)&woh, g_woh); cudaGetSymbolAddress((void**)&wol, g_wol);
    cudaGetSymbolAddress((void**)&aoh, g_aoh); cudaGetSymbolAddress((void**)&aol, g_aol);

    cudaFuncSetAttribute(gemm3seg,  cudaFuncAttributeMaxDynamicSharedMemorySize, 2*4*128*40*2);
    cudaFuncSetAttribute(attn_kernel, cudaFuncAttributeMaxDynamicSharedMemorySize, ATTN_SMEM_BYTES);

    cvt_all_kernel<<<5120, 256>>>(x, wq, wk, wv, wo);
    router_kernel<<<S_/4, 128>>>(x, wr);
    build_lists_kernel<<<1, 192>>>();
    aux_reduce_kernel<<<1, 256>>>(out, out_size);

    // fused Q/K/V projections (bf16 hi/lo inputs)
    gemm3seg<<<dim3(24, 8, 1), 256, 2*4*128*40*2>>>(
        xh, xl, wqh, wql, wkh, wkl, wvh, wvl, yq, yk, yv,
        EMB_, 12, 6, M_*QH_*D_, M_*D_, M_*D_);

    gather_rope_kernel<<<E_, 128>>>();
    attn_kernel<<<dim3(E_/64, QH_, M_), 128, ATTN_SMEM_BYTES>>>();

    // output projection, split-K=2
    gemm3seg<<<dim3(8, 8, 2), 256, 2*4*128*40*2>>>(
        aoh, aol, woh, wol, nullptr, nullptr, nullptr, nullptr, part, nullptr, nullptr,
        EMB_, 8, 0, EMB_, 0, 0);
    add_out_kernel<<<S_*EMB_/256, 256>>>(out);
}

// round 7
// speedup vs baseline: 1.1308x; 1.1308x over previous
#include <cuda_runtime.h>
#include <cuda_bf16.h>
#include <math.h>
#include <stdint.h>

#define S_    1024
#define EMB_  1024
#define M_    6
#define A_    4
#define QH_   2
#define D_    128
#define E_    (S_*A_)

typedef __nv_bfloat16 bf16;

// ---------------- scratch ----------------
__device__ float g_yq[S_*M_*QH_*D_];
__device__ float g_yk[S_*M_*D_];
__device__ float g_yv[S_*M_*D_];
__device__ float g_auxp[256*13];
__device__ int   g_kvidx[E_];
__device__ float g_kvw[E_];
__device__ int   g_rank[E_];
__device__ int   g_list[M_*E_];
__device__ int   g_counts[M_];
__device__ bf16  g_xh[S_*EMB_],       g_xl[S_*EMB_];
__device__ bf16  g_wqh[1536*EMB_],    g_wql[1536*EMB_];
__device__ bf16  g_wkh[768*EMB_],     g_wkl[768*EMB_];
__device__ bf16  g_wvh[768*EMB_],     g_wvl[768*EMB_];
__device__ bf16  g_woh[EMB_*EMB_],    g_wol[EMB_*EMB_];
__device__ bf16  g_qh[M_*E_*QH_*D_],  g_ql[M_*E_*QH_*D_];
__device__ bf16  g_kh[M_*E_*D_],      g_kl[M_*E_*D_];
__device__ bf16  g_vth[M_*D_*E_],     g_vtl[M_*D_*E_];
__device__ bf16  g_aoh[S_*A_*QH_*D_], g_aol[S_*A_*QH_*D_];
__device__ float g_part[2*S_*EMB_];

// ---------------- helpers ----------------
__device__ __forceinline__ uint32_t smem_u32(const void* p) {
    return (uint32_t)__cvta_generic_to_shared(p);
}
__device__ __forceinline__ void ldsm4(uint32_t* r, const void* p) {
    uint32_t a = smem_u32(p);
    asm volatile("ldmatrix.sync.aligned.m8n8.x4.shared.b16 {%0,%1,%2,%3}, [%4];"
                 : "=r"(r[0]), "=r"(r[1]), "=r"(r[2]), "=r"(r[3]) : "r"(a));
}
__device__ __forceinline__ void mma16816(float* c, const uint32_t* a, uint32_t b0, uint32_t b1) {
    asm volatile("mma.sync.aligned.m16n8k16.row.col.f32.bf16.bf16.f32 "
                 "{%0,%1,%2,%3}, {%4,%5,%6,%7}, {%8,%9}, {%0,%1,%2,%3};"
                 : "+f"(c[0]), "+f"(c[1]), "+f"(c[2]), "+f"(c[3])
                 : "r"(a[0]), "r"(a[1]), "r"(a[2]), "r"(a[3]), "r"(b0), "r"(b1));
}
__device__ __forceinline__ void cp16(void* smem, const void* gmem) {
    asm volatile("cp.async.cg.shared.global [%0], [%1], 16;"
                 :: "r"(smem_u32(smem)), "l"(gmem));
}
__device__ __forceinline__ void cp_commit() { asm volatile("cp.async.commit_group;"); }
__device__ __forceinline__ void cp_wait1()  { asm volatile("cp.async.wait_group 1;"); }

__device__ __forceinline__ void cvt4(float4 v, uint2& hi, uint2& lo) {
    bf16 h0 = __float2bfloat16(v.x), h1 = __float2bfloat16(v.y);
    bf16 h2 = __float2bfloat16(v.z), h3 = __float2bfloat16(v.w);
    bf16 l0 = __float2bfloat16(v.x - __bfloat162float(h0));
    bf16 l1 = __float2bfloat16(v.y - __bfloat162float(h1));
    bf16 l2 = __float2bfloat16(v.z - __bfloat162float(h2));
    bf16 l3 = __float2bfloat16(v.w - __bfloat162float(h3));
    __nv_bfloat162 H0, H1, L0, L1;
    H0.x = h0; H0.y = h1; H1.x = h2; H1.y = h3;
    L0.x = l0; L0.y = l1; L1.x = l2; L1.y = l3;
    hi.x = *(uint32_t*)&H0; hi.y = *(uint32_t*)&H1;
    lo.x = *(uint32_t*)&L0; lo.y = *(uint32_t*)&L1;
}
__device__ __forceinline__ void packhl(float x, float y, uint32_t& hi, uint32_t& lo) {
    __nv_bfloat162 H, L;
    H.x = __float2bfloat16(x); H.y = __float2bfloat16(y);
    L.x = __float2bfloat16(x - __bfloat162float(H.x));
    L.y = __float2bfloat16(y - __bfloat162float(H.y));
    hi = *(uint32_t*)&H; lo = *(uint32_t*)&L;
}
__device__ __forceinline__ void splitf(float v, bf16& h, bf16& l) {
    h = __float2bfloat16(v);
    l = __float2bfloat16(v - __bfloat162float(h));
}

// ---------------- one-shot hi/lo conversion ----------------
__global__ void cvt_all_kernel(const float* __restrict__ x,  const float* __restrict__ wq,
                               const float* __restrict__ wk, const float* __restrict__ wv,
                               const float* __restrict__ wo) {
    int i = blockIdx.x * 256 + threadIdx.x;
    const float* src; bf16 *dh, *dl; int off;
    if (i < 262144)        { src = x;  dh = g_xh;  dl = g_xl;  off = i; }
    else if (i < 655360)   { src = wq; dh = g_wqh; dl = g_wql; off = i - 262144; }
    else if (i < 851968)   { src = wk; dh = g_wkh; dl = g_wkl; off = i - 655360; }
    else if (i < 1048576)  { src = wv; dh = g_wvh; dl = g_wvl; off = i - 851968; }
    else                   { src = wo; dh = g_woh; dl = g_wol; off = i - 1048576; }
    float4 v = ((const float4*)src)[off];
    uint2 h, l;
    cvt4(v, h, l);
    ((uint2*)dh)[off] = h;
    ((uint2*)dl)[off] = l;
}

// ---------------- router: logits/topk/weights + per-block aux partials ----------------
__global__ void router_kernel(const float* __restrict__ x, const float* __restrict__ wr) {
    __shared__ float sf[4][13];
    int w    = threadIdx.x >> 5;
    int gw   = blockIdx.x * 4 + w;
    int lane = threadIdx.x & 31;
    const float* xr = x + gw * EMB_;
    float acc[M_];
#pragma unroll
    for (int m = 0; m < M_; m++) acc[m] = 0.f;
    for (int i = lane; i < EMB_; i += 32) {
        float xv = xr[i];
#pragma unroll
        for (int m = 0; m < M_; m++) acc[m] += xv * wr[m*EMB_ + i];
    }
#pragma unroll
    for (int m = 0; m < M_; m++)
        for (int o = 16; o; o >>= 1) acc[m] += __shfl_xor_sync(0xffffffffu, acc[m], o);
    if (lane == 0) {
        float mx = acc[0];
#pragma unroll
        for (int m = 1; m < M_; m++) mx = fmaxf(mx, acc[m]);
        float ex[M_], ssum = 0.f;
#pragma unroll
        for (int m = 0; m < M_; m++) { ex[m] = expf(acc[m] - mx); ssum += ex[m]; }
        float inv = 1.f / ssum;
        float ent = 0.f;
#pragma unroll
        for (int m = 0; m < M_; m++) {
            float p = ex[m] * inv;
            sf[w][6 + m] = p;
            ent -= p * logf(p + 1e-8f);
        }
        sf[w][12] = ent;
        float v[M_];
#pragma unroll
        for (int m = 0; m < M_; m++) v[m] = acc[m];
        int   idx[A_]; float tv[A_];
#pragma unroll
        for (int a = 0; a < A_; a++) {
            float best = -INFINITY; int bi = 0;
#pragma unroll
            for (int m = 0; m < M_; m++) if (v[m] > best) { best = v[m]; bi = m; }
            idx[a] = bi; tv[a] = best; v[bi] = -INFINITY;
        }
        float wv[A_], ws = 0.f;
#pragma unroll
        for (int a = 0; a < A_; a++) { wv[a] = expf(tv[a] - tv[0]); ws += wv[a]; }
        float winv = 1.f / ws;
#pragma unroll
        for (int a = 0; a < A_; a++) {
            g_kvidx[gw*A_ + a] = idx[a];
            g_kvw  [gw*A_ + a] = wv[a] * winv;
        }
#pragma unroll
        for (int m = 0; m < M_; m++) sf[w][m] = (idx[0] == m) ? 1.f : 0.f;
    }
    __syncthreads();
    if (threadIdx.x < 13)
        g_auxp[blockIdx.x*13 + threadIdx.x] =
            sf[0][threadIdx.x] + sf[1][threadIdx.x] + sf[2][threadIdx.x] + sf[3][threadIdx.x];
}

// ---------------- final aux reduction (256 partial rows x 13) ----------------
__global__ void aux_final_kernel(float* __restrict__ d_out, int out_size) {
    __shared__ float tot[16];
    int w = threadIdx.x >> 5, lane = threadIdx.x & 31;
#pragma unroll
    for (int qq = 0; qq < 2; qq++) {
        int q = w*2 + qq;
        if (q < 13) {
            float s = 0.f;
#pragma unroll
            for (int r = 0; r < 8; r++) s += g_auxp[(lane + r*32)*13 + q];
            for (int o = 16; o; o >>= 1) s += __shfl_xor_sync(0xffffffffu, s, o);
            if (lane == 0) tot[q] = s;
        }
    }
    __syncthreads();
    if (threadIdx.x == 0) {
        float bal = 0.f;
#pragma unroll
        for (int m = 0; m < M_; m++) bal += (tot[m] / (float)S_) * (tot[6+m] / (float)S_);
        bal *= (float)M_;
        d_out[out_size - 1] = 0.01f * bal - 0.01f * (tot[12] / (float)S_);
    }
}

// ---------------- per-expert lists + ranks ----------------
__global__ void build_lists_kernel() {
    int m    = threadIdx.x >> 5;
    int lane = threadIdx.x & 31;
    if (m >= M_) return;
    int base = 0;
    for (int e0 = 0; e0 < E_; e0 += 32) {
        int e = e0 + lane;
        int gidx = g_kvidx[e];
        unsigned mask = __ballot_sync(0xffffffffu, gidx == m);
        if (gidx == m) {
            int r = base + __popc(mask & ((1u << lane) - 1u));
            g_rank[e] = r;
            g_list[m*E_ + r] = e;
        }
        base += __popc(mask);
    }
    if (lane == 0) g_counts[m] = base;
}

// ---------------- GEMM: cp.async 2-stage, 2 CTAs/SM, bf16 hi/lo 3-pass ----------------
#define GST (4*128*40)   // bf16 elems per stage
__global__ __launch_bounds__(256, 2) void gemm3seg(
    const bf16* __restrict__ Ah, const bf16* __restrict__ Al,
    const bf16* __restrict__ B0h, const bf16* __restrict__ B0l,
    const bf16* __restrict__ B1h, const bf16* __restrict__ B1l,
    const bf16* __restrict__ B2h, const bf16* __restrict__ B2l,
    float* __restrict__ C0, float* __restrict__ C1, float* __restrict__ C2,
    int K, int nb0, int nb1, int N0, int N1, int N2)
{
    extern __shared__ bf16 ds[];
    int tid = threadIdx.x, lane = tid & 31, warp = tid >> 5;
    int wm = warp >> 1, wn = warp & 1;

    int Klen = K / gridDim.z;
    int kOff = blockIdx.z * Klen;

    const bf16 *Bph, *Bpl; float* Cp; int N; int bxl = blockIdx.x;
    if (bxl < nb0)             { Bph = B0h; Bpl = B0l; Cp = C0; N = N0; }
    else if (bxl < nb0 + nb1)  { Bph = B1h; Bpl = B1l; Cp = C1; N = N1; bxl -= nb0; }
    else                       { Bph = B2h; Bpl = B2l; Cp = C2; N = N2; bxl -= nb0 + nb1; }
    Cp += (size_t)blockIdx.z * S_ * N;

    int crow = tid >> 1;
    int ckk  = (tid & 1) * 16;
    const bf16* ga0 = Ah  + (size_t)(blockIdx.y*128 + crow) * K + kOff + ckk;
    const bf16* ga1 = Al  + (size_t)(blockIdx.y*128 + crow) * K + kOff + ckk;
    const bf16* gb0 = Bph + (size_t)(bxl       *128 + crow) * K + kOff + ckk;
    const bf16* gb1 = Bpl + (size_t)(bxl       *128 + crow) * K + kOff + ckk;
    int so = crow*40 + ckk;

    float acc[2][8][4];
#pragma unroll
    for (int mt = 0; mt < 2; mt++)
#pragma unroll
        for (int nt = 0; nt < 8; nt++)
#pragma unroll
            for (int c = 0; c < 4; c++) acc[mt][nt][c] = 0.f;

    int g   = lane >> 3;
    int lr  = (lane & 7) + ((g & 1) << 3);
    int lcA = (g >> 1) << 3;
    int brn = (lane & 7) + ((g >> 1) << 3);
    int lcB = (g & 1) << 3;

    // prologue: stages 0 (kt=0) and 1 (kt=32)
#pragma unroll
    for (int s = 0; s < 2; s++) {
        bf16* st = ds + s*GST;
        int kk = s*32;
        cp16(st +            so,     ga0 + kk); cp16(st +            so + 8, ga0 + kk + 8);
        cp16(st +   128*40 + so,     ga1 + kk); cp16(st +   128*40 + so + 8, ga1 + kk + 8);
        cp16(st + 2*128*40 + so,     gb0 + kk); cp16(st + 2*128*40 + so + 8, gb0 + kk + 8);
        cp16(st + 3*128*40 + so,     gb1 + kk); cp16(st + 3*128*40 + so + 8, gb1 + kk + 8);
        cp_commit();
    }

    for (int kt = 0; kt < Klen; kt += 32) {
        int cur = (kt >> 5) & 1;
        cp_wait1();
        __syncthreads();
        const bf16* Ahi = ds + cur*GST;
        const bf16* Alo = Ahi + 128*40;
        const bf16* Bhi = Ahi + 2*128*40;
        const bf16* Blo = Ahi + 3*128*40;
#pragma unroll
        for (int kh = 0; kh < 2; kh++) {
            uint32_t ah[2][4], al[2][4];
#pragma unroll
            for (int mt = 0; mt < 2; mt++) {
                int r = wm*32 + mt*16 + lr;
                int c = kh*16 + lcA;
                ldsm4(ah[mt], &Ahi[r*40 + c]);
                ldsm4(al[mt], &Alo[r*40 + c]);
            }
#pragma unroll
            for (int nt2 = 0; nt2 < 4; nt2++) {
                uint32_t bh[4], bl[4];
                int r = wn*64 + nt2*16 + brn;
                int c = kh*16 + lcB;
                ldsm4(bh, &Bhi[r*40 + c]);
                ldsm4(bl, &Blo[r*40 + c]);
                mma16816(acc[0][2*nt2],   ah[0], bh[0], bh[1]);
                mma16816(acc[1][2*nt2],   ah[1], bh[0], bh[1]);
                mma16816(acc[0][2*nt2+1], ah[0], bh[2], bh[3]);
                mma16816(acc[1][2*nt2+1], ah[1], bh[2], bh[3]);
                mma16816(acc[0][2*nt2],   ah[0], bl[0], bl[1]);
                mma16816(acc[1][2*nt2],   ah[1], bl[0], bl[1]);
                mma16816(acc[0][2*nt2+1], ah[0], bl[2], bl[3]);
                mma16816(acc[1][2*nt2+1], ah[1], bl[2], bl[3]);
                mma16816(acc[0][2*nt2],   al[0], bh[0], bh[1]);
                mma16816(acc[1][2*nt2],   al[1], bh[0], bh[1]);
                mma16816(acc[0][2*nt2+1], al[0], bh[2], bh[3]);
                mma16816(acc[1][2*nt2+1], al[1], bh[2], bh[3]);
            }
        }
        __syncthreads();
        if (kt + 64 < Klen) {
            bf16* st = ds + cur*GST;
            int kk = kt + 64;
            cp16(st +            so,     ga0 + kk); cp16(st +            so + 8, ga0 + kk + 8);
            cp16(st +   128*40 + so,     ga1 + kk); cp16(st +   128*40 + so + 8, ga1 + kk + 8);
            cp16(st + 2*128*40 + so,     gb0 + kk); cp16(st + 2*128*40 + so + 8, gb0 + kk + 8);
            cp16(st + 3*128*40 + so,     gb1 + kk); cp16(st + 3*128*40 + so + 8, gb1 + kk + 8);
        }
        cp_commit();
    }

    int crow0 = blockIdx.y*128 + wm*32 + (lane >> 2);
    int ccol0 = bxl*128 + wn*64 + (lane & 3)*2;
#pragma unroll
    for (int mt = 0; mt < 2; mt++)
#pragma unroll
        for (int nt = 0; nt < 8; nt++) {
            float* p = Cp + (size_t)(crow0 + mt*16) * N + ccol0 + nt*8;
            *(float2*)p           = make_float2(acc[mt][nt][0], acc[mt][nt][1]);
            *(float2*)(p + 8*N)   = make_float2(acc[mt][nt][2], acc[mt][nt][3]);
        }
}

// ---------------- sum split-K partials ----------------
__global__ void add_out_kernel(float* __restrict__ out) {
    int i = blockIdx.x * 256 + threadIdx.x;
    out[i] = g_part[i] + g_part[i + S_*EMB_];
}

// ---------------- gather + RoPE -> bf16 hi/lo ----------------
__global__ void gather_rope_kernel() {
    int e = blockIdx.x;
    int d = threadIdx.x;
    int m = g_kvidx[e];
    int r = g_rank[e];
    int t = e >> 2;
    int dm = d & 63;
    float invf = expf(-(float)dm * (9.210340371976184f / 64.0f));
    float fr = (float)r * invf;
    float sn, cs;
    sincosf(fr, &sn, &cs);
    int   partner = (d < 64) ? d + 64 : d - 64;
    float sgn     = (d < 64) ? -1.f : 1.f;
    int ro = m * E_ + r;
    const float scale = 0.08838834764831845f;
    const float* kb = g_yk + t * (M_ * D_) + m * D_;
    float kvv = kb[d] * cs + sgn * kb[partner] * sn;
    splitf(kvv, g_kh[ro*D_ + d], g_kl[ro*D_ + d]);
    float vv = g_yv[t*(M_*D_) + m*D_ + d];
    splitf(vv, g_vth[(m*D_ + d)*E_ + r], g_vtl[(m*D_ + d)*E_ + r]);
#pragma unroll
    for (int h = 0; h < QH_; h++) {
        const float* qb = g_yq + t * (M_*QH_*D_) + (m*QH_ + h) * D_;
        float qv = (qb[d] * cs + sgn * qb[partner] * sn) * scale;
        splitf(qv, g_qh[(ro*QH_ + h)*D_ + d], g_ql[(ro*QH_ + h)*D_ + d]);
    }
}

// ---------------- tensor-core flash attention ----------------
#define AQH0 0
#define AQL0 8704
#define AKH0 17408
#define AKL0 26112
#define AVH0 34816
#define AVL0 44032
#define ATTN_SMEM_BYTES (53248*2)

__global__ __launch_bounds__(128) void attn_kernel() {
    int m = blockIdx.z, h = blockIdx.y;
    int L = g_counts[m];
    int q0 = blockIdx.x * 64;
    if (q0 >= L) return;

    extern __shared__ bf16 as[];
    int tid = threadIdx.x, lane = tid & 31, wm = tid >> 5;

    int g   = lane >> 3;
    int lr  = (lane & 7) + ((g & 1) << 3);
    int lcA = (g >> 1) << 3;
    int brn = (lane & 7) + ((g >> 1) << 3);
    int lcB = (g & 1) << 3;
    int cb  = (lane & 3) * 2;

    for (int idx = tid; idx < 64*16; idx += 128) {
        int i = idx >> 4, dq = (idx & 15) * 8;
        size_t go = (((size_t)(m*E_ + q0 + i)*QH_ + h) << 7) + dq;
        *(uint4*)&as[AQH0 + i*136 + dq] = *(const uint4*)(g_qh + go);
        *(uint4*)&as[AQL0 + i*136 + dq] = *(const uint4*)(g_ql + go);
    }

    float Oa[16][4];
#pragma unroll
    for (int nt = 0; nt < 16; nt++)
#pragma unroll
        for (int c = 0; c < 4; c++) Oa[nt][c] = 0.f;
    float mrow[2] = {-INFINITY, -INFINITY};
    float lrow[2] = {0.f, 0.f};

    for (int kt = 0; kt < L; kt += 64) {
        __syncthreads();
        for (int idx = tid; idx < 64*16; idx += 128) {
            int j = idx >> 4, dq = (idx & 15) * 8;
            size_t go = (((size_t)(m*E_ + kt + j)) << 7) + dq;
            *(uint4*)&as[AKH0 + j*136 + dq] = *(const uint4*)(g_kh + go);
            *(uint4*)&as[AKL0 + j*136 + dq] = *(const uint4*)(g_kl + go);
        }
        for (int idx = tid; idx < 128*8; idx += 128) {
            int d = idx >> 3, jq = (idx & 7) * 8;
            size_t go = ((size_t)(m*D_ + d))*E_ + kt + jq;
            *(uint4*)&as[AVH0 + d*72 + jq] = *(const uint4*)(g_vth + go);
            *(uint4*)&as[AVL0 + d*72 + jq] = *(const uint4*)(g_vtl + go);
        }
        __syncthreads();

        float Sacc[8][4];
#pragma unroll
        for (int nt = 0; nt < 8; nt++)
#pragma unroll
            for (int c = 0; c < 4; c++) Sacc[nt][c] = 0.f;
#pragma unroll
        for (int kc = 0; kc < 8; kc++) {
            uint32_t qh[4], ql[4], bh[4][4], bl[4][4];
            ldsm4(qh, &as[AQH0 + (wm*16 + lr)*136 + kc*16 + lcA]);
            ldsm4(ql, &as[AQL0 + (wm*16 + lr)*136 + kc*16 + lcA]);
#pragma unroll
            for (int nt2 = 0; nt2 < 4; nt2++) {
                ldsm4(bh[nt2], &as[AKH0 + (nt2*16 + brn)*136 + kc*16 + lcB]);
                ldsm4(bl[nt2], &as[AKL0 + (nt2*16 + brn)*136 + kc*16 + lcB]);
            }
#pragma unroll
            for (int nt2 = 0; nt2 < 4; nt2++) {
                mma16816(Sacc[2*nt2],   qh, bh[nt2][0], bh[nt2][1]);
                mma16816(Sacc[2*nt2+1], qh, bh[nt2][2], bh[nt2][3]);
            }
#pragma unroll
            for (int nt2 = 0; nt2 < 4; nt2++) {
                mma16816(Sacc[2*nt2],   qh, bl[nt2][0], bl[nt2][1]);
                mma16816(Sacc[2*nt2+1], qh, bl[nt2][2], bl[nt2][3]);
            }
#pragma unroll
            for (int nt2 = 0; nt2 < 4; nt2++) {
                mma16816(Sacc[2*nt2],   ql, bh[nt2][0], bh[nt2][1]);
                mma16816(Sacc[2*nt2+1], ql, bh[nt2][2], bh[nt2][3]);
            }
        }

        int lim = L - kt;
#pragma unroll
        for (int nt = 0; nt < 8; nt++) {
            int c0 = nt*8 + cb;
            if (c0     >= lim) { Sacc[nt][0] = -1e30f; Sacc[nt][2] = -1e30f; }
            if (c0 + 1 >= lim) { Sacc[nt][1] = -1e30f; Sacc[nt][3] = -1e30f; }
        }
#pragma unroll
        for (int rr = 0; rr < 2; rr++) {
            float mx = -INFINITY;
#pragma unroll
            for (int nt = 0; nt < 8; nt++)
                mx = fmaxf(mx, fmaxf(Sacc[nt][rr*2], Sacc[nt][rr*2+1]));
            mx = fmaxf(mx, __shfl_xor_sync(0xffffffffu, mx, 1));
            mx = fmaxf(mx, __shfl_xor_sync(0xffffffffu, mx, 2));
            float mn = fmaxf(mrow[rr], mx);
            float corr = __expf(mrow[rr] - mn);
            mrow[rr] = mn;
            float ps = 0.f;
#pragma unroll
            for (int nt = 0; nt < 8; nt++) {
                float p0 = __expf(Sacc[nt][rr*2]   - mn);
                float p1 = __expf(Sacc[nt][rr*2+1] - mn);
                Sacc[nt][rr*2] = p0; Sacc[nt][rr*2+1] = p1;
                ps += p0 + p1;
            }
            ps += __shfl_xor_sync(0xffffffffu, ps, 1);
            ps += __shfl_xor_sync(0xffffffffu, ps, 2);
            lrow[rr] = lrow[rr] * corr + ps;
#pragma unroll
            for (int nt = 0; nt < 16; nt++) {
                Oa[nt][rr*2]   *= corr;
                Oa[nt][rr*2+1] *= corr;
            }
        }

#pragma unroll
        for (int kc2 = 0; kc2 < 4; kc2++) {
            uint32_t pah[4], pal[4];
            packhl(Sacc[2*kc2][0],   Sacc[2*kc2][1],   pah[0], pal[0]);
            packhl(Sacc[2*kc2][2],   Sacc[2*kc2][3],   pah[1], pal[1]);
            packhl(Sacc[2*kc2+1][0], Sacc[2*kc2+1][1], pah[2], pal[2]);
            packhl(Sacc[2*kc2+1][2], Sacc[2*kc2+1][3], pah[3], pal[3]);
#pragma unroll
            for (int nt2 = 0; nt2 < 8; nt2++) {
                uint32_t vh[4], vl[4];
                ldsm4(vh, &as[AVH0 + (nt2*16 + brn)*72 + kc2*16 + lcB]);
                ldsm4(vl, &as[AVL0 + (nt2*16 + brn)*72 + kc2*16 + lcB]);
                mma16816(Oa[2*nt2],   pah, vh[0], vh[1]);
                mma16816(Oa[2*nt2+1], pah, vh[2], vh[3]);
                mma16816(Oa[2*nt2],   pah, vl[0], vl[1]);
                mma16816(Oa[2*nt2+1], pah, vl[2], vl[3]);
                mma16816(Oa[2*nt2],   pal, vh[0], vh[1]);
                mma16816(Oa[2*nt2+1], pal, vh[2], vh[3]);
            }
        }
    }

#pragma unroll
    for (int rr = 0; rr < 2; rr++) {
        int row_local = wm*16 + (lane >> 2) + 8*rr;
        int gr = q0 + row_local;
        if (gr < L) {
            int e = g_list[m*E_ + gr];
            int t = e >> 2, a = e & 3;
            float w = g_kvw[t*A_ + a] / lrow[rr];
            size_t base = (size_t)t*(A_*QH_*D_) + (a*QH_ + h)*D_;
#pragma unroll
            for (int nt = 0; nt < 16; nt++) {
                int col = nt*8 + cb;
                uint32_t hi, lo;
                packhl(Oa[nt][rr*2]*w, Oa[nt][rr*2+1]*w, hi, lo);
                *(uint32_t*)(g_aoh + base + col) = hi;
                *(uint32_t*)(g_aol + base + col) = lo;
            }
        }
    }
}

// ---------------- launch ----------------
extern "C" void kernel_launch(void* const* d_in, const int* in_sizes, int n_in,
                              void* d_out, int out_size)
{
    const float* x  = (const float*)d_in[0];
    const float* wq = (const float*)d_in[1];
    const float* wk = (const float*)d_in[2];
    const float* wv = (const float*)d_in[3];
    const float* wr = (const float*)d_in[4];
    const float* wo = (const float*)d_in[5];
    float* out = (float*)d_out;

    float *yq, *yk, *yv, *part;
    bf16 *xh, *xl, *wqh, *wql, *wkh, *wkl, *wvh, *wvl, *woh, *wol, *aoh, *aol;
    cudaGetSymbolAddress((void**)&yq, g_yq);
    cudaGetSymbolAddress((void**)&yk, g_yk);
    cudaGetSymbolAddress((void**)&yv, g_yv);
    cudaGetSymbolAddress((void**)&part, g_part);
    cudaGetSymbolAddress((void**)&xh,  g_xh);  cudaGetSymbolAddress((void**)&xl,  g_xl);
    cudaGetSymbolAddress((void**)&wqh, g_wqh); cudaGetSymbolAddress((void**)&wql, g_wql);
    cudaGetSymbolAddress((void**)&wkh, g_wkh); cudaGetSymbolAddress((void**)&wkl, g_wkl);
    cudaGetSymbolAddress((void**)&wvh, g_wvh); cudaGetSymbolAddress((void**)&wvl, g_wvl);
    cudaGetSymbolAddress((void**)&woh, g_woh); cudaGetSymbolAddress((void**)&wol, g_wol);
    cudaGetSymbolAddress((void**)&aoh, g_aoh); cudaGetSymbolAddress((void**)&aol, g_aol);

    cudaFuncSetAttribute(gemm3seg,    cudaFuncAttributeMaxDynamicSharedMemorySize, 2*GST*2);
    cudaFuncSetAttribute(attn_kernel, cudaFuncAttributeMaxDynamicSharedMemorySize, ATTN_SMEM_BYTES);

    cvt_all_kernel<<<5120, 256>>>(x, wq, wk, wv, wo);
    router_kernel<<<S_/4, 128>>>(x, wr);
    build_lists_kernel<<<1, 192>>>();
    aux_final_kernel<<<1, 256>>>(out, out_size);

    gemm3seg<<<dim3(24, 8, 1), 256, 2*GST*2>>>(
        xh, xl, wqh, wql, wkh, wkl, wvh, wvl, yq, yk, yv,
        EMB_, 12, 6, M_*QH_*D_, M_*D_, M_*D_);

    gather_rope_kernel<<<E_, 128>>>();
    attn_kernel<<<dim3(E_/64, QH_, M_), 128, ATTN_SMEM_BYTES>>>();

    gemm3seg<<<dim3(8, 8, 2), 256, 2*GST*2>>>(
        aoh, aol, woh, wol, nullptr, nullptr, nullptr, nullptr, part, nullptr, nullptr,
        EMB_, 8, 0, EMB_, 0, 0);
    add_out_kernel<<<S_*EMB_/256, 256>>>(out);
}

// round 10
// speedup vs baseline: 1.2690x; 1.1222x over previous
#include <cuda_runtime.h>
#include <cuda_bf16.h>
#include <math.h>
#include <stdint.h>

#define S_    1024
#define EMB_  1024
#define M_    6
#define A_    4
#define QH_   2
#define D_    128
#define E_    (S_*A_)

typedef __nv_bfloat16 bf16;

// ---------------- scratch ----------------
// QKV projection outputs hold 2 split-K partials each: [z][S][N]
__device__ float g_yq[2*S_*M_*QH_*D_];
__device__ float g_yk[2*S_*M_*D_];
__device__ float g_yv[2*S_*M_*D_];
__device__ float g_auxp[256*13];
__device__ int   g_kvidx[E_];
__device__ float g_kvw[E_];
__device__ int   g_rank[E_];
__device__ int   g_list[M_*E_];
__device__ int   g_counts[M_];
__device__ bf16  g_xh[S_*EMB_],       g_xl[S_*EMB_];
__device__ bf16  g_wqh[1536*EMB_],    g_wql[1536*EMB_];
__device__ bf16  g_wkh[768*EMB_],     g_wkl[768*EMB_];
__device__ bf16  g_wvh[768*EMB_],     g_wvl[768*EMB_];
__device__ bf16  g_woh[EMB_*EMB_],    g_wol[EMB_*EMB_];
__device__ bf16  g_qh[M_*E_*QH_*D_],  g_ql[M_*E_*QH_*D_];
__device__ bf16  g_kh[M_*E_*D_],      g_kl[M_*E_*D_];
__device__ bf16  g_vth[M_*D_*E_],     g_vtl[M_*D_*E_];
__device__ bf16  g_aoh[S_*A_*QH_*D_], g_aol[S_*A_*QH_*D_];
__device__ float g_part[2*S_*EMB_];

// ---------------- helpers ----------------
__device__ __forceinline__ uint32_t smem_u32(const void* p) {
    return (uint32_t)__cvta_generic_to_shared(p);
}
__device__ __forceinline__ void ldsm4(uint32_t* r, const void* p) {
    uint32_t a = smem_u32(p);
    asm volatile("ldmatrix.sync.aligned.m8n8.x4.shared.b16 {%0,%1,%2,%3}, [%4];"
                 : "=r"(r[0]), "=r"(r[1]), "=r"(r[2]), "=r"(r[3]) : "r"(a));
}
__device__ __forceinline__ void mma16816(float* c, const uint32_t* a, uint32_t b0, uint32_t b1) {
    asm volatile("mma.sync.aligned.m16n8k16.row.col.f32.bf16.bf16.f32 "
                 "{%0,%1,%2,%3}, {%4,%5,%6,%7}, {%8,%9}, {%0,%1,%2,%3};"
                 : "+f"(c[0]), "+f"(c[1]), "+f"(c[2]), "+f"(c[3])
                 : "r"(a[0]), "r"(a[1]), "r"(a[2]), "r"(a[3]), "r"(b0), "r"(b1));
}
__device__ __forceinline__ void cp16(void* smem, const void* gmem) {
    asm volatile("cp.async.cg.shared.global [%0], [%1], 16;"
                 :: "r"(smem_u32(smem)), "l"(gmem));
}
__device__ __forceinline__ void cp_commit() { asm volatile("cp.async.commit_group;"); }
__device__ __forceinline__ void cp_wait1()  { asm volatile("cp.async.wait_group 1;"); }

__device__ __forceinline__ void cvt4(float4 v, uint2& hi, uint2& lo) {
    bf16 h0 = __float2bfloat16(v.x), h1 = __float2bfloat16(v.y);
    bf16 h2 = __float2bfloat16(v.z), h3 = __float2bfloat16(v.w);
    bf16 l0 = __float2bfloat16(v.x - __bfloat162float(h0));
    bf16 l1 = __float2bfloat16(v.y - __bfloat162float(h1));
    bf16 l2 = __float2bfloat16(v.z - __bfloat162float(h2));
    bf16 l3 = __float2bfloat16(v.w - __bfloat162float(h3));
    __nv_bfloat162 H0, H1, L0, L1;
    H0.x = h0; H0.y = h1; H1.x = h2; H1.y = h3;
    L0.x = l0; L0.y = l1; L1.x = l2; L1.y = l3;
    hi.x = *(uint32_t*)&H0; hi.y = *(uint32_t*)&H1;
    lo.x = *(uint32_t*)&L0; lo.y = *(uint32_t*)&L1;
}
__device__ __forceinline__ void packhl(float x, float y, uint32_t& hi, uint32_t& lo) {
    __nv_bfloat162 H, L;
    H.x = __float2bfloat16(x); H.y = __float2bfloat16(y);
    L.x = __float2bfloat16(x - __bfloat162float(H.x));
    L.y = __float2bfloat16(y - __bfloat162float(H.y));
    hi = *(uint32_t*)&H; lo = *(uint32_t*)&L;
}
__device__ __forceinline__ void splitf(float v, bf16& h, bf16& l) {
    h = __float2bfloat16(v);
    l = __float2bfloat16(v - __bfloat162float(h));
}

// ---------------- one-shot hi/lo conversion ----------------
__global__ void cvt_all_kernel(const float* __restrict__ x,  const float* __restrict__ wq,
                               const float* __restrict__ wk, const float* __restrict__ wv,
                               const float* __restrict__ wo) {
    int i = blockIdx.x * 256 + threadIdx.x;
    const float* src; bf16 *dh, *dl; int off;
    if (i < 262144)        { src = x;  dh = g_xh;  dl = g_xl;  off = i; }
    else if (i < 655360)   { src = wq; dh = g_wqh; dl = g_wql; off = i - 262144; }
    else if (i < 851968)   { src = wk; dh = g_wkh; dl = g_wkl; off = i - 655360; }
    else if (i < 1048576)  { src = wv; dh = g_wvh; dl = g_wvl; off = i - 851968; }
    else                   { src = wo; dh = g_woh; dl = g_wol; off = i - 1048576; }
    float4 v = ((const float4*)src)[off];
    uint2 h, l;
    cvt4(v, h, l);
    ((uint2*)dh)[off] = h;
    ((uint2*)dl)[off] = l;
}

// ---------------- router: logits/topk/weights + per-block aux partials ----------------
__global__ void router_kernel(const float* __restrict__ x, const float* __restrict__ wr) {
    __shared__ float sf[4][13];
    int w    = threadIdx.x >> 5;
    int gw   = blockIdx.x * 4 + w;
    int lane = threadIdx.x & 31;
    const float* xr = x + gw * EMB_;
    float acc[M_];
#pragma unroll
    for (int m = 0; m < M_; m++) acc[m] = 0.f;
    for (int i = lane; i < EMB_; i += 32) {
        float xv = xr[i];
#pragma unroll
        for (int m = 0; m < M_; m++) acc[m] += xv * wr[m*EMB_ + i];
    }
#pragma unroll
    for (int m = 0; m < M_; m++)
        for (int o = 16; o; o >>= 1) acc[m] += __shfl_xor_sync(0xffffffffu, acc[m], o);
    if (lane == 0) {
        float mx = acc[0];
#pragma unroll
        for (int m = 1; m < M_; m++) mx = fmaxf(mx, acc[m]);
        float ex[M_], ssum = 0.f;
#pragma unroll
        for (int m = 0; m < M_; m++) { ex[m] = expf(acc[m] - mx); ssum += ex[m]; }
        float inv = 1.f / ssum;
        float ent = 0.f;
#pragma unroll
        for (int m = 0; m < M_; m++) {
            float p = ex[m] * inv;
            sf[w][6 + m] = p;
            ent -= p * logf(p + 1e-8f);
        }
        sf[w][12] = ent;
        float v[M_];
#pragma unroll
        for (int m = 0; m < M_; m++) v[m] = acc[m];
        int   idx[A_]; float tv[A_];
#pragma unroll
        for (int a = 0; a < A_; a++) {
            float best = -INFINITY; int bi = 0;
#pragma unroll
            for (int m = 0; m < M_; m++) if (v[m] > best) { best = v[m]; bi = m; }
            idx[a] = bi; tv[a] = best; v[bi] = -INFINITY;
        }
        float wv[A_], ws = 0.f;
#pragma unroll
        for (int a = 0; a < A_; a++) { wv[a] = expf(tv[a] - tv[0]); ws += wv[a]; }
        float winv = 1.f / ws;
#pragma unroll
        for (int a = 0; a < A_; a++) {
            g_kvidx[gw*A_ + a] = idx[a];
            g_kvw  [gw*A_ + a] = wv[a] * winv;
        }
#pragma unroll
        for (int m = 0; m < M_; m++) sf[w][m] = (idx[0] == m) ? 1.f : 0.f;
    }
    __syncthreads();
    if (threadIdx.x < 13)
        g_auxp[blockIdx.x*13 + threadIdx.x] =
            sf[0][threadIdx.x] + sf[1][threadIdx.x] + sf[2][threadIdx.x] + sf[3][threadIdx.x];
}

// ---------------- final aux reduction ----------------
__global__ void aux_final_kernel(float* __restrict__ d_out, int out_size) {
    __shared__ float tot[16];
    int w = threadIdx.x >> 5, lane = threadIdx.x & 31;
#pragma unroll
    for (int qq = 0; qq < 2; qq++) {
        int q = w*2 + qq;
        if (q < 13) {
            float s = 0.f;
#pragma unroll
            for (int r = 0; r < 8; r++) s += g_auxp[(lane + r*32)*13 + q];
            for (int o = 16; o; o >>= 1) s += __shfl_xor_sync(0xffffffffu, s, o);
            if (lane == 0) tot[q] = s;
        }
    }
    __syncthreads();
    if (threadIdx.x == 0) {
        float bal = 0.f;
#pragma unroll
        for (int m = 0; m < M_; m++) bal += (tot[m] / (float)S_) * (tot[6+m] / (float)S_);
        bal *= (float)M_;
        d_out[out_size - 1] = 0.01f * bal - 0.01f * (tot[12] / (float)S_);
    }
}

// ---------------- per-expert lists + ranks ----------------
__global__ void build_lists_kernel() {
    int m    = threadIdx.x >> 5;
    int lane = threadIdx.x & 31;
    if (m >= M_) return;
    int base = 0;
    for (int e0 = 0; e0 < E_; e0 += 32) {
        int e = e0 + lane;
        int gidx = g_kvidx[e];
        unsigned mask = __ballot_sync(0xffffffffu, gidx == m);
        if (gidx == m) {
            int r = base + __popc(mask & ((1u << lane) - 1u));
            g_rank[e] = r;
            g_list[m*E_ + r] = e;
        }
        base += __popc(mask);
    }
    if (lane == 0) g_counts[m] = base;
}

// ---------------- GEMM: cp.async 2-stage, 2 CTAs/SM, bf16 hi/lo 3-pass, split-K ----------------
#define GST (4*128*40)   // bf16 elems per stage
__global__ __launch_bounds__(256, 2) void gemm3seg(
    const bf16* __restrict__ Ah, const bf16* __restrict__ Al,
    const bf16* __restrict__ B0h, const bf16* __restrict__ B0l,
    const bf16* __restrict__ B1h, const bf16* __restrict__ B1l,
    const bf16* __restrict__ B2h, const bf16* __restrict__ B2l,
    float* __restrict__ C0, float* __restrict__ C1, float* __restrict__ C2,
    int K, int nb0, int nb1, int N0, int N1, int N2)
{
    extern __shared__ bf16 ds[];
    int tid = threadIdx.x, lane = tid & 31, warp = tid >> 5;
    int wm = warp >> 1, wn = warp & 1;

    int Klen = K / gridDim.z;
    int kOff = blockIdx.z * Klen;

    const bf16 *Bph, *Bpl; float* Cp; int N; int bxl = blockIdx.x;
    if (bxl < nb0)             { Bph = B0h; Bpl = B0l; Cp = C0; N = N0; }
    else if (bxl < nb0 + nb1)  { Bph = B1h; Bpl = B1l; Cp = C1; N = N1; bxl -= nb0; }
    else                       { Bph = B2h; Bpl = B2l; Cp = C2; N = N2; bxl -= nb0 + nb1; }
    Cp += (size_t)blockIdx.z * S_ * N;   // split-K partial slab

    int crow = tid >> 1;
    int ckk  = (tid & 1) * 16;
    const bf16* ga0 = Ah  + (size_t)(blockIdx.y*128 + crow) * K + kOff + ckk;
    const bf16* ga1 = Al  + (size_t)(blockIdx.y*128 + crow) * K + kOff + ckk;
    const bf16* gb0 = Bph + (size_t)(bxl       *128 + crow) * K + kOff + ckk;
    const bf16* gb1 = Bpl + (size_t)(bxl       *128 + crow) * K + kOff + ckk;
    int so = crow*40 + ckk;

    float acc[2][8][4];
#pragma unroll
    for (int mt = 0; mt < 2; mt++)
#pragma unroll
        for (int nt = 0; nt < 8; nt++)
#pragma unroll
            for (int c = 0; c < 4; c++) acc[mt][nt][c] = 0.f;

    int g   = lane >> 3;
    int lr  = (lane & 7) + ((g & 1) << 3);
    int lcA = (g >> 1) << 3;
    int brn = (lane & 7) + ((g >> 1) << 3);
    int lcB = (g & 1) << 3;

    // prologue: stages 0 (kt=0) and 1 (kt=32)
#pragma unroll
    for (int s = 0; s < 2; s++) {
        bf16* st = ds + s*GST;
        int kk = s*32;
        cp16(st +            so,     ga0 + kk); cp16(st +            so + 8, ga0 + kk + 8);
        cp16(st +   128*40 + so,     ga1 + kk); cp16(st +   128*40 + so + 8, ga1 + kk + 8);
        cp16(st + 2*128*40 + so,     gb0 + kk); cp16(st + 2*128*40 + so + 8, gb0 + kk + 8);
        cp16(st + 3*128*40 + so,     gb1 + kk); cp16(st + 3*128*40 + so + 8, gb1 + kk + 8);
        cp_commit();
    }

    for (int kt = 0; kt < Klen; kt += 32) {
        int cur = (kt >> 5) & 1;
        cp_wait1();
        __syncthreads();
        const bf16* Ahi = ds + cur*GST;
        const bf16* Alo = Ahi + 128*40;
        const bf16* Bhi = Ahi + 2*128*40;
        const bf16* Blo = Ahi + 3*128*40;
#pragma unroll
        for (int kh = 0; kh < 2; kh++) {
            uint32_t ah[2][4], al[2][4];
#pragma unroll
            for (int mt = 0; mt < 2; mt++) {
                int r = wm*32 + mt*16 + lr;
                int c = kh*16 + lcA;
                ldsm4(ah[mt], &Ahi[r*40 + c]);
                ldsm4(al[mt], &Alo[r*40 + c]);
            }
#pragma unroll
            for (int nt2 = 0; nt2 < 4; nt2++) {
                uint32_t bh[4], bl[4];
                int r = wn*64 + nt2*16 + brn;
                int c = kh*16 + lcB;
                ldsm4(bh, &Bhi[r*40 + c]);
                ldsm4(bl, &Blo[r*40 + c]);
                mma16816(acc[0][2*nt2],   ah[0], bh[0], bh[1]);
                mma16816(acc[1][2*nt2],   ah[1], bh[0], bh[1]);
                mma16816(acc[0][2*nt2+1], ah[0], bh[2], bh[3]);
                mma16816(acc[1][2*nt2+1], ah[1], bh[2], bh[3]);
                mma16816(acc[0][2*nt2],   ah[0], bl[0], bl[1]);
                mma16816(acc[1][2*nt2],   ah[1], bl[0], bl[1]);
                mma16816(acc[0][2*nt2+1], ah[0], bl[2], bl[3]);
                mma16816(acc[1][2*nt2+1], ah[1], bl[2], bl[3]);
                mma16816(acc[0][2*nt2],   al[0], bh[0], bh[1]);
                mma16816(acc[1][2*nt2],   al[1], bh[0], bh[1]);
                mma16816(acc[0][2*nt2+1], al[0], bh[2], bh[3]);
                mma16816(acc[1][2*nt2+1], al[1], bh[2], bh[3]);
            }
        }
        __syncthreads();
        if (kt + 64 < Klen) {
            bf16* st = ds + cur*GST;
            int kk = kt + 64;
            cp16(st +            so,     ga0 + kk); cp16(st +            so + 8, ga0 + kk + 8);
            cp16(st +   128*40 + so,     ga1 + kk); cp16(st +   128*40 + so + 8, ga1 + kk + 8);
            cp16(st + 2*128*40 + so,     gb0 + kk); cp16(st + 2*128*40 + so + 8, gb0 + kk + 8);
            cp16(st + 3*128*40 + so,     gb1 + kk); cp16(st + 3*128*40 + so + 8, gb1 + kk + 8);
        }
        cp_commit();
    }

    int crow0 = blockIdx.y*128 + wm*32 + (lane >> 2);
    int ccol0 = bxl*128 + wn*64 + (lane & 3)*2;
#pragma unroll
    for (int mt = 0; mt < 2; mt++)
#pragma unroll
        for (int nt = 0; nt < 8; nt++) {
            float* p = Cp + (size_t)(crow0 + mt*16) * N + ccol0 + nt*8;
            *(float2*)p           = make_float2(acc[mt][nt][0], acc[mt][nt][1]);
            *(float2*)(p + 8*N)   = make_float2(acc[mt][nt][2], acc[mt][nt][3]);
        }
}

// ---------------- sum split-K partials (out projection) ----------------
__global__ void add_out_kernel(float* __restrict__ out) {
    int i = blockIdx.x * 256 + threadIdx.x;
    out[i] = g_part[i] + g_part[i + S_*EMB_];
}

// ---------------- gather + RoPE -> bf16 hi/lo (sums QKV split-K partials inline) ----------------
__global__ void gather_rope_kernel() {
    int e = blockIdx.x;
    int d = threadIdx.x;
    int m = g_kvidx[e];
    int r = g_rank[e];
    int t = e >> 2;
    int dm = d & 63;
    float invf = expf(-(float)dm * (9.210340371976184f / 64.0f));
    float fr = (float)r * invf;
    float sn, cs;
    sincosf(fr, &sn, &cs);
    int   partner = (d < 64) ? d + 64 : d - 64;
    float sgn     = (d < 64) ? -1.f : 1.f;
    int ro = m * E_ + r;
    const float scale = 0.08838834764831845f;
    const float* kb  = g_yk + t * (M_ * D_) + m * D_;
    const float* kb2 = kb + S_*M_*D_;
    float kvv = (kb[d] + kb2[d]) * cs + sgn * (kb[partner] + kb2[partner]) * sn;
    splitf(kvv, g_kh[ro*D_ + d], g_kl[ro*D_ + d]);
    int vo = t*(M_*D_) + m*D_ + d;
    float vv = g_yv[vo] + g_yv[vo + S_*M_*D_];
    splitf(vv, g_vth[(m*D_ + d)*E_ + r], g_vtl[(m*D_ + d)*E_ + r]);
#pragma unroll
    for (int h = 0; h < QH_; h++) {
        const float* qb  = g_yq + t * (M_*QH_*D_) + (m*QH_ + h) * D_;
        const float* qb2 = qb + S_*M_*QH_*D_;
        float qv = ((qb[d] + qb2[d]) * cs + sgn * (qb[partner] + qb2[partner]) * sn) * scale;
        splitf(qv, g_qh[(ro*QH_ + h)*D_ + d], g_ql[(ro*QH_ + h)*D_ + d]);
    }
}

// ---------------- tensor-core flash attention ----------------
#define AQH0 0
#define AQL0 8704
#define AKH0 17408
#define AKL0 26112
#define AVH0 34816
#define AVL0 44032
#define ATTN_SMEM_BYTES (53248*2)

__global__ __launch_bounds__(128) void attn_kernel() {
    int m = blockIdx.z, h = blockIdx.y;
    int L = g_counts[m];
    int q0 = blockIdx.x * 64;
    if (q0 >= L) return;

    extern __shared__ bf16 as[];
    int tid = threadIdx.x, lane = tid & 31, wm = tid >> 5;

    int g   = lane >> 3;
    int lr  = (lane & 7) + ((g & 1) << 3);
    int lcA = (g >> 1) << 3;
    int brn = (lane & 7) + ((g >> 1) << 3);
    int lcB = (g & 1) << 3;
    int cb  = (lane & 3) * 2;

    for (int idx = tid; idx < 64*16; idx += 128) {
        int i = idx >> 4, dq = (idx & 15) * 8;
        size_t go = (((size_t)(m*E_ + q0 + i)*QH_ + h) << 7) + dq;
        *(uint4*)&as[AQH0 + i*136 + dq] = *(const uint4*)(g_qh + go);
        *(uint4*)&as[AQL0 + i*136 + dq] = *(const uint4*)(g_ql + go);
    }

    float Oa[16][4];
#pragma unroll
    for (int nt = 0; nt < 16; nt++)
#pragma unroll
        for (int c = 0; c < 4; c++) Oa[nt][c] = 0.f;
    float mrow[2] = {-INFINITY, -INFINITY};
    float lrow[2] = {0.f, 0.f};

    for (int kt = 0; kt < L; kt += 64) {
        __syncthreads();
        for (int idx = tid; idx < 64*16; idx += 128) {
            int j = idx >> 4, dq = (idx & 15) * 8;
            size_t go = (((size_t)(m*E_ + kt + j)) << 7) + dq;
            *(uint4*)&as[AKH0 + j*136 + dq] = *(const uint4*)(g_kh + go);
            *(uint4*)&as[AKL0 + j*136 + dq] = *(const uint4*)(g_kl + go);
        }
        for (int idx = tid; idx < 128*8; idx += 128) {
            int d = idx >> 3, jq = (idx & 7) * 8;
            size_t go = ((size_t)(m*D_ + d))*E_ + kt + jq;
            *(uint4*)&as[AVH0 + d*72 + jq] = *(const uint4*)(g_vth + go);
            *(uint4*)&as[AVL0 + d*72 + jq] = *(const uint4*)(g_vtl + go);
        }
        __syncthreads();

        float Sacc[8][4];
#pragma unroll
        for (int nt = 0; nt < 8; nt++)
#pragma unroll
            for (int c = 0; c < 4; c++) Sacc[nt][c] = 0.f;
#pragma unroll
        for (int kc = 0; kc < 8; kc++) {
            uint32_t qh[4], ql[4], bh[4][4], bl[4][4];
            ldsm4(qh, &as[AQH0 + (wm*16 + lr)*136 + kc*16 + lcA]);
            ldsm4(ql, &as[AQL0 + (wm*16 + lr)*136 + kc*16 + lcA]);
#pragma unroll
            for (int nt2 = 0; nt2 < 4; nt2++) {
                ldsm4(bh[nt2], &as[AKH0 + (nt2*16 + brn)*136 + kc*16 + lcB]);
                ldsm4(bl[nt2], &as[AKL0 + (nt2*16 + brn)*136 + kc*16 + lcB]);
            }
#pragma unroll
            for (int nt2 = 0; nt2 < 4; nt2++) {
                mma16816(Sacc[2*nt2],   qh, bh[nt2][0], bh[nt2][1]);
                mma16816(Sacc[2*nt2+1], qh, bh[nt2][2], bh[nt2][3]);
            }
#pragma unroll
            for (int nt2 = 0; nt2 < 4; nt2++) {
                mma16816(Sacc[2*nt2],   qh, bl[nt2][0], bl[nt2][1]);
                mma16816(Sacc[2*nt2+1], qh, bl[nt2][2], bl[nt2][3]);
            }
#pragma unroll
            for (int nt2 = 0; nt2 < 4; nt2++) {
                mma16816(Sacc[2*nt2],   ql, bh[nt2][0], bh[nt2][1]);
                mma16816(Sacc[2*nt2+1], ql, bh[nt2][2], bh[nt2][3]);
            }
        }

        int lim = L - kt;
#pragma unroll
        for (int nt = 0; nt < 8; nt++) {
            int c0 = nt*8 + cb;
            if (c0     >= lim) { Sacc[nt][0] = -1e30f; Sacc[nt][2] = -1e30f; }
            if (c0 + 1 >= lim) { Sacc[nt][1] = -1e30f; Sacc[nt][3] = -1e30f; }
        }
#pragma unroll
        for (int rr = 0; rr < 2; rr++) {
            float mx = -INFINITY;
#pragma unroll
            for (int nt = 0; nt < 8; nt++)
                mx = fmaxf(mx, fmaxf(Sacc[nt][rr*2], Sacc[nt][rr*2+1]));
            mx = fmaxf(mx, __shfl_xor_sync(0xffffffffu, mx, 1));
            mx = fmaxf(mx, __shfl_xor_sync(0xffffffffu, mx, 2));
            float mn = fmaxf(mrow[rr], mx);
            float corr = __expf(mrow[rr] - mn);
            mrow[rr] = mn;
            float ps = 0.f;
#pragma unroll
            for (int nt = 0; nt < 8; nt++) {
                float p0 = __expf(Sacc[nt][rr*2]   - mn);
                float p1 = __expf(Sacc[nt][rr*2+1] - mn);
                Sacc[nt][rr*2] = p0; Sacc[nt][rr*2+1] = p1;
                ps += p0 + p1;
            }
            ps += __shfl_xor_sync(0xffffffffu, ps, 1);
            ps += __shfl_xor_sync(0xffffffffu, ps, 2);
            lrow[rr] = lrow[rr] * corr + ps;
#pragma unroll
            for (int nt = 0; nt < 16; nt++) {
                Oa[nt][rr*2]   *= corr;
                Oa[nt][rr*2+1] *= corr;
            }
        }

#pragma unroll
        for (int kc2 = 0; kc2 < 4; kc2++) {
            uint32_t pah[4], pal[4];
            packhl(Sacc[2*kc2][0],   Sacc[2*kc2][1],   pah[0], pal[0]);
            packhl(Sacc[2*kc2][2],   Sacc[2*kc2][3],   pah[1], pal[1]);
            packhl(Sacc[2*kc2+1][0], Sacc[2*kc2+1][1], pah[2], pal[2]);
            packhl(Sacc[2*kc2+1][2], Sacc[2*kc2+1][3], pah[3], pal[3]);
#pragma unroll
            for (int nt2 = 0; nt2 < 8; nt2++) {
                uint32_t vh[4], vl[4];
                ldsm4(vh, &as[AVH0 + (nt2*16 + brn)*72 + kc2*16 + lcB]);
                ldsm4(vl, &as[AVL0 + (nt2*16 + brn)*72 + kc2*16 + lcB]);
                mma16816(Oa[2*nt2],   pah, vh[0], vh[1]);
                mma16816(Oa[2*nt2+1], pah, vh[2], vh[3]);
                mma16816(Oa[2*nt2],   pah, vl[0], vl[1]);
                mma16816(Oa[2*nt2+1], pah, vl[2], vl[3]);
                mma16816(Oa[2*nt2],   pal, vh[0], vh[1]);
                mma16816(Oa[2*nt2+1], pal, vh[2], vh[3]);
            }
        }
    }

#pragma unroll
    for (int rr = 0; rr < 2; rr++) {
        int row_local = wm*16 + (lane >> 2) + 8*rr;
        int gr = q0 + row_local;
        if (gr < L) {
            int e = g_list[m*E_ + gr];
            int t = e >> 2, a = e & 3;
            float w = g_kvw[t*A_ + a] / lrow[rr];
            size_t base = (size_t)t*(A_*QH_*D_) + (a*QH_ + h)*D_;
#pragma unroll
            for (int nt = 0; nt < 16; nt++) {
                int col = nt*8 + cb;
                uint32_t hi, lo;
                packhl(Oa[nt][rr*2]*w, Oa[nt][rr*2+1]*w, hi, lo);
                *(uint32_t*)(g_aoh + base + col) = hi;
                *(uint32_t*)(g_aol + base + col) = lo;
            }
        }
    }
}

// ---------------- launch ----------------
extern "C" void kernel_launch(void* const* d_in, const int* in_sizes, int n_in,
                              void* d_out, int out_size)
{
    const float* x  = (const float*)d_in[0];
    const float* wq = (const float*)d_in[1];
    const float* wk = (const float*)d_in[2];
    const float* wv = (const float*)d_in[3];
    const float* wr = (const float*)d_in[4];
    const float* wo = (const float*)d_in[5];
    float* out = (float*)d_out;

    float *yq, *yk, *yv, *part;
    bf16 *xh, *xl, *wqh, *wql, *wkh, *wkl, *wvh, *wvl, *woh, *wol, *aoh, *aol;
    cudaGetSymbolAddress((void**)&yq, g_yq);
    cudaGetSymbolAddress((void**)&yk, g_yk);
    cudaGetSymbolAddress((void**)&yv, g_yv);
    cudaGetSymbolAddress((void**)&part, g_part);
    cudaGetSymbolAddress((void**)&xh,  g_xh);  cudaGetSymbolAddress((void**)&xl,  g_xl);
    cudaGetSymbolAddress((void**)&wqh, g_wqh); cudaGetSymbolAddress((void**)&wql, g_wql);
    cudaGetSymbolAddress((void**)&wkh, g_wkh); cudaGetSymbolAddress((void**)&wkl, g_wkl);
    cudaGetSymbolAddress((void**)&wvh, g_wvh); cudaGetSymbolAddress((void**)&wvl, g_wvl);
    cudaGetSymbolAddress((void**)&woh, g_woh); cudaGetSymbolAddress((void**)&wol, g_wol);
    cudaGetSymbolAddress((void**)&aoh, g_aoh); cudaGetSymbolAddress((void**)&aol, g_aol);

    cudaFuncSetAttribute(gemm3seg,    cudaFuncAttributeMaxDynamicSharedMemorySize, 2*GST*2);
    cudaFuncSetAttribute(attn_kernel, cudaFuncAttributeMaxDynamicSharedMemorySize, ATTN_SMEM_BYTES);

    cvt_all_kernel<<<5120, 256>>>(x, wq, wk, wv, wo);
    router_kernel<<<S_/4, 128>>>(x, wr);
    build_lists_kernel<<<1, 192>>>();
    aux_final_kernel<<<1, 256>>>(out, out_size);

    // fused Q/K/V projections, split-K=2 (384 CTAs; partials summed in gather_rope)
    gemm3seg<<<dim3(24, 8, 2), 256, 2*GST*2>>>(
        xh, xl, wqh, wql, wkh, wkl, wvh, wvl, yq, yk, yv,
        EMB_, 12, 6, M_*QH_*D_, M_*D_, M_*D_);

    gather_rope_kernel<<<E_, 128>>>();
    attn_kernel<<<dim3(E_/64, QH_, M_), 128, ATTN_SMEM_BYTES>>>();

    // output projection, split-K=2
    gemm3seg<<<dim3(8, 8, 2), 256, 2*GST*2>>>(
        aoh, aol, woh, wol, nullptr, nullptr, nullptr, nullptr, part, nullptr, nullptr,
        EMB_, 8, 0, EMB_, 0, 0);
    add_out_kernel<<<S_*EMB_/256, 256>>>(out);
}

// round 16
// speedup vs baseline: 1.3895x; 1.0950x over previous
#include <cuda_runtime.h>
#include <cuda_bf16.h>
#include <math.h>
#include <stdint.h>

#define S_    1024
#define EMB_  1024
#define M_    6
#define A_    4
#define QH_   2
#define D_    128
#define E_    (S_*A_)

typedef __nv_bfloat16 bf16;

// ---------------- scratch ----------------
__device__ float g_yq[2*S_*M_*QH_*D_];
__device__ float g_yk[2*S_*M_*D_];
__device__ float g_yv[2*S_*M_*D_];
__device__ float g_auxp[256*13];
__device__ int   g_kvidx[E_];
__device__ float g_kvw[E_];
__device__ int   g_rank[E_];
__device__ int   g_list[M_*E_];
__device__ int   g_counts[M_];
__device__ bf16  g_xh[S_*EMB_],       g_xl[S_*EMB_];
__device__ bf16  g_wqh[1536*EMB_],    g_wql[1536*EMB_];
__device__ bf16  g_wkh[768*EMB_],     g_wkl[768*EMB_];
__device__ bf16  g_wvh[768*EMB_],     g_wvl[768*EMB_];
__device__ bf16  g_woh[EMB_*EMB_],    g_wol[EMB_*EMB_];
__device__ bf16  g_qh[M_*E_*QH_*D_],  g_ql[M_*E_*QH_*D_];
__device__ bf16  g_kh[M_*E_*D_],      g_kl[M_*E_*D_];
__device__ bf16  g_vth[M_*D_*E_],     g_vtl[M_*D_*E_];
__device__ bf16  g_aoh[S_*A_*QH_*D_], g_aol[S_*A_*QH_*D_];
__device__ float g_part[2*S_*EMB_];
// split-KV attention partials: [sp][(m*E+r)*QH+h]
__device__ float g_pO[2][M_*E_*QH_][D_];
__device__ float g_pm[2][M_*E_*QH_];
__device__ float g_pl[2][M_*E_*QH_];

// ---------------- helpers ----------------
__device__ __forceinline__ uint32_t smem_u32(const void* p) {
    return (uint32_t)__cvta_generic_to_shared(p);
}
__device__ __forceinline__ void ldsm4(uint32_t* r, const void* p) {
    uint32_t a = smem_u32(p);
    asm volatile("ldmatrix.sync.aligned.m8n8.x4.shared.b16 {%0,%1,%2,%3}, [%4];"
                 : "=r"(r[0]), "=r"(r[1]), "=r"(r[2]), "=r"(r[3]) : "r"(a));
}
__device__ __forceinline__ void mma16816(float* c, const uint32_t* a, uint32_t b0, uint32_t b1) {
    asm volatile("mma.sync.aligned.m16n8k16.row.col.f32.bf16.bf16.f32 "
                 "{%0,%1,%2,%3}, {%4,%5,%6,%7}, {%8,%9}, {%0,%1,%2,%3};"
                 : "+f"(c[0]), "+f"(c[1]), "+f"(c[2]), "+f"(c[3])
                 : "r"(a[0]), "r"(a[1]), "r"(a[2]), "r"(a[3]), "r"(b0), "r"(b1));
}
__device__ __forceinline__ void cp16(void* smem, const void* gmem) {
    asm volatile("cp.async.cg.shared.global [%0], [%1], 16;"
                 :: "r"(smem_u32(smem)), "l"(gmem));
}
__device__ __forceinline__ void cp_commit() { asm volatile("cp.async.commit_group;"); }
__device__ __forceinline__ void cp_wait1()  { asm volatile("cp.async.wait_group 1;"); }

__device__ __forceinline__ void cvt4(float4 v, uint2& hi, uint2& lo) {
    bf16 h0 = __float2bfloat16(v.x), h1 = __float2bfloat16(v.y);
    bf16 h2 = __float2bfloat16(v.z), h3 = __float2bfloat16(v.w);
    bf16 l0 = __float2bfloat16(v.x - __bfloat162float(h0));
    bf16 l1 = __float2bfloat16(v.y - __bfloat162float(h1));
    bf16 l2 = __float2bfloat16(v.z - __bfloat162float(h2));
    bf16 l3 = __float2bfloat16(v.w - __bfloat162float(h3));
    __nv_bfloat162 H0, H1, L0, L1;
    H0.x = h0; H0.y = h1; H1.x = h2; H1.y = h3;
    L0.x = l0; L0.y = l1; L1.x = l2; L1.y = l3;
    hi.x = *(uint32_t*)&H0; hi.y = *(uint32_t*)&H1;
    lo.x = *(uint32_t*)&L0; lo.y = *(uint32_t*)&L1;
}
__device__ __forceinline__ void packhl(float x, float y, uint32_t& hi, uint32_t& lo) {
    __nv_bfloat162 H, L;
    H.x = __float2bfloat16(x); H.y = __float2bfloat16(y);
    L.x = __float2bfloat16(x - __bfloat162float(H.x));
    L.y = __float2bfloat16(y - __bfloat162float(H.y));
    hi = *(uint32_t*)&H; lo = *(uint32_t*)&L;
}
__device__ __forceinline__ void splitf(float v, bf16& h, bf16& l) {
    h = __float2bfloat16(v);
    l = __float2bfloat16(v - __bfloat162float(h));
}

// ---------------- one-shot hi/lo conversion ----------------
__global__ void cvt_all_kernel(const float* __restrict__ x,  const float* __restrict__ wq,
                               const float* __restrict__ wk, const float* __restrict__ wv,
                               const float* __restrict__ wo) {
    int i = blockIdx.x * 256 + threadIdx.x;
    const float* src; bf16 *dh, *dl; int off;
    if (i < 262144)        { src = x;  dh = g_xh;  dl = g_xl;  off = i; }
    else if (i < 655360)   { src = wq; dh = g_wqh; dl = g_wql; off = i - 262144; }
    else if (i < 851968)   { src = wk; dh = g_wkh; dl = g_wkl; off = i - 655360; }
    else if (i < 1048576)  { src = wv; dh = g_wvh; dl = g_wvl; off = i - 851968; }
    else                   { src = wo; dh = g_woh; dl = g_wol; off = i - 1048576; }
    float4 v = ((const float4*)src)[off];
    uint2 h, l;
    cvt4(v, h, l);
    ((uint2*)dh)[off] = h;
    ((uint2*)dl)[off] = l;
}

// ---------------- router ----------------
__global__ void router_kernel(const float* __restrict__ x, const float* __restrict__ wr) {
    __shared__ float sf[4][13];
    int w    = threadIdx.x >> 5;
    int gw   = blockIdx.x * 4 + w;
    int lane = threadIdx.x & 31;
    const float* xr = x + gw * EMB_;
    float acc[M_];
#pragma unroll
    for (int m = 0; m < M_; m++) acc[m] = 0.f;
    for (int i = lane; i < EMB_; i += 32) {
        float xv = xr[i];
#pragma unroll
        for (int m = 0; m < M_; m++) acc[m] += xv * wr[m*EMB_ + i];
    }
#pragma unroll
    for (int m = 0; m < M_; m++)
        for (int o = 16; o; o >>= 1) acc[m] += __shfl_xor_sync(0xffffffffu, acc[m], o);
    if (lane == 0) {
        float mx = acc[0];
#pragma unroll
        for (int m = 1; m < M_; m++) mx = fmaxf(mx, acc[m]);
        float ex[M_], ssum = 0.f;
#pragma unroll
        for (int m = 0; m < M_; m++) { ex[m] = expf(acc[m] - mx); ssum += ex[m]; }
        float inv = 1.f / ssum;
        float ent = 0.f;
#pragma unroll
        for (int m = 0; m < M_; m++) {
            float p = ex[m] * inv;
            sf[w][6 + m] = p;
            ent -= p * logf(p + 1e-8f);
        }
        sf[w][12] = ent;
        float v[M_];
#pragma unroll
        for (int m = 0; m < M_; m++) v[m] = acc[m];
        int   idx[A_]; float tv[A_];
#pragma unroll
        for (int a = 0; a < A_; a++) {
            float best = -INFINITY; int bi = 0;
#pragma unroll
            for (int m = 0; m < M_; m++) if (v[m] > best) { best = v[m]; bi = m; }
            idx[a] = bi; tv[a] = best; v[bi] = -INFINITY;
        }
        float wv[A_], ws = 0.f;
#pragma unroll
        for (int a = 0; a < A_; a++) { wv[a] = expf(tv[a] - tv[0]); ws += wv[a]; }
        float winv = 1.f / ws;
#pragma unroll
        for (int a = 0; a < A_; a++) {
            g_kvidx[gw*A_ + a] = idx[a];
            g_kvw  [gw*A_ + a] = wv[a] * winv;
        }
#pragma unroll
        for (int m = 0; m < M_; m++) sf[w][m] = (idx[0] == m) ? 1.f : 0.f;
    }
    __syncthreads();
    if (threadIdx.x < 13)
        g_auxp[blockIdx.x*13 + threadIdx.x] =
            sf[0][threadIdx.x] + sf[1][threadIdx.x] + sf[2][threadIdx.x] + sf[3][threadIdx.x];
}

// ---------------- final aux reduction ----------------
__global__ void aux_final_kernel(float* __restrict__ d_out, int out_size) {
    __shared__ float tot[16];
    int w = threadIdx.x >> 5, lane = threadIdx.x & 31;
#pragma unroll
    for (int qq = 0; qq < 2; qq++) {
        int q = w*2 + qq;
        if (q < 13) {
            float s = 0.f;
#pragma unroll
            for (int r = 0; r < 8; r++) s += g_auxp[(lane + r*32)*13 + q];
            for (int o = 16; o; o >>= 1) s += __shfl_xor_sync(0xffffffffu, s, o);
            if (lane == 0) tot[q] = s;
        }
    }
    __syncthreads();
    if (threadIdx.x == 0) {
        float bal = 0.f;
#pragma unroll
        for (int m = 0; m < M_; m++) bal += (tot[m] / (float)S_) * (tot[6+m] / (float)S_);
        bal *= (float)M_;
        d_out[out_size - 1] = 0.01f * bal - 0.01f * (tot[12] / (float)S_);
    }
}

// ---------------- per-expert lists + ranks ----------------
__global__ void build_lists_kernel() {
    int m    = threadIdx.x >> 5;
    int lane = threadIdx.x & 31;
    if (m >= M_) return;
    int base = 0;
    for (int e0 = 0; e0 < E_; e0 += 32) {
        int e = e0 + lane;
        int gidx = g_kvidx[e];
        unsigned mask = __ballot_sync(0xffffffffu, gidx == m);
        if (gidx == m) {
            int r = base + __popc(mask & ((1u << lane) - 1u));
            g_rank[e] = r;
            g_list[m*E_ + r] = e;
        }
        base += __popc(mask);
    }
    if (lane == 0) g_counts[m] = base;
}

// ---------------- GEMM: cp.async 2-stage, 2 CTAs/SM, bf16 hi/lo 3-pass, split-K ----------------
#define GST (4*128*40)
__global__ __launch_bounds__(256, 2) void gemm3seg(
    const bf16* __restrict__ Ah, const bf16* __restrict__ Al,
    const bf16* __restrict__ B0h, const bf16* __restrict__ B0l,
    const bf16* __restrict__ B1h, const bf16* __restrict__ B1l,
    const bf16* __restrict__ B2h, const bf16* __restrict__ B2l,
    float* __restrict__ C0, float* __restrict__ C1, float* __restrict__ C2,
    int K, int nb0, int nb1, int N0, int N1, int N2)
{
    extern __shared__ bf16 ds[];
    int tid = threadIdx.x, lane = tid & 31, warp = tid >> 5;
    int wm = warp >> 1, wn = warp & 1;

    int Klen = K / gridDim.z;
    int kOff = blockIdx.z * Klen;

    const bf16 *Bph, *Bpl; float* Cp; int N; int bxl = blockIdx.x;
    if (bxl < nb0)             { Bph = B0h; Bpl = B0l; Cp = C0; N = N0; }
    else if (bxl < nb0 + nb1)  { Bph = B1h; Bpl = B1l; Cp = C1; N = N1; bxl -= nb0; }
    else                       { Bph = B2h; Bpl = B2l; Cp = C2; N = N2; bxl -= nb0 + nb1; }
    Cp += (size_t)blockIdx.z * S_ * N;

    int crow = tid >> 1;
    int ckk  = (tid & 1) * 16;
    const bf16* ga0 = Ah  + (size_t)(blockIdx.y*128 + crow) * K + kOff + ckk;
    const bf16* ga1 = Al  + (size_t)(blockIdx.y*128 + crow) * K + kOff + ckk;
    const bf16* gb0 = Bph + (size_t)(bxl       *128 + crow) * K + kOff + ckk;
    const bf16* gb1 = Bpl + (size_t)(bxl       *128 + crow) * K + kOff + ckk;
    int so = crow*40 + ckk;

    float acc[2][8][4];
#pragma unroll
    for (int mt = 0; mt < 2; mt++)
#pragma unroll
        for (int nt = 0; nt < 8; nt++)
#pragma unroll
            for (int c = 0; c < 4; c++) acc[mt][nt][c] = 0.f;

    int g   = lane >> 3;
    int lr  = (lane & 7) + ((g & 1) << 3);
    int lcA = (g >> 1) << 3;
    int brn = (lane & 7) + ((g >> 1) << 3);
    int lcB = (g & 1) << 3;

#pragma unroll
    for (int s = 0; s < 2; s++) {
        bf16* st = ds + s*GST;
        int kk = s*32;
        cp16(st +            so,     ga0 + kk); cp16(st +            so + 8, ga0 + kk + 8);
        cp16(st +   128*40 + so,     ga1 + kk); cp16(st +   128*40 + so + 8, ga1 + kk + 8);
        cp16(st + 2*128*40 + so,     gb0 + kk); cp16(st + 2*128*40 + so + 8, gb0 + kk + 8);
        cp16(st + 3*128*40 + so,     gb1 + kk); cp16(st + 3*128*40 + so + 8, gb1 + kk + 8);
        cp_commit();
    }

    for (int kt = 0; kt < Klen; kt += 32) {
        int cur = (kt >> 5) & 1;
        cp_wait1();
        __syncthreads();
        const bf16* Ahi = ds + cur*GST;
        const bf16* Alo = Ahi + 128*40;
        const bf16* Bhi = Ahi + 2*128*40;
        const bf16* Blo = Ahi + 3*128*40;
#pragma unroll
        for (int kh = 0; kh < 2; kh++) {
            uint32_t ah[2][4], al[2][4];
#pragma unroll
            for (int mt = 0; mt < 2; mt++) {
                int r = wm*32 + mt*16 + lr;
                int c = kh*16 + lcA;
                ldsm4(ah[mt], &Ahi[r*40 + c]);
                ldsm4(al[mt], &Alo[r*40 + c]);
            }
#pragma unroll
            for (int nt2 = 0; nt2 < 4; nt2++) {
                uint32_t bh[4], bl[4];
                int r = wn*64 + nt2*16 + brn;
                int c = kh*16 + lcB;
                ldsm4(bh, &Bhi[r*40 + c]);
                ldsm4(bl, &Blo[r*40 + c]);
                mma16816(acc[0][2*nt2],   ah[0], bh[0], bh[1]);
                mma16816(acc[1][2*nt2],   ah[1], bh[0], bh[1]);
                mma16816(acc[0][2*nt2+1], ah[0], bh[2], bh[3]);
                mma16816(acc[1][2*nt2+1], ah[1], bh[2], bh[3]);
                mma16816(acc[0][2*nt2],   ah[0], bl[0], bl[1]);
                mma16816(acc[1][2*nt2],   ah[1], bl[0], bl[1]);
                mma16816(acc[0][2*nt2+1], ah[0], bl[2], bl[3]);
                mma16816(acc[1][2*nt2+1], ah[1], bl[2], bl[3]);
                mma16816(acc[0][2*nt2],   al[0], bh[0], bh[1]);
                mma16816(acc[1][2*nt2],   al[1], bh[0], bh[1]);
                mma16816(acc[0][2*nt2+1], al[0], bh[2], bh[3]);
                mma16816(acc[1][2*nt2+1], al[1], bh[2], bh[3]);
            }
        }
        __syncthreads();
        if (kt + 64 < Klen) {
            bf16* st = ds + cur*GST;
            int kk = kt + 64;
            cp16(st +            so,     ga0 + kk); cp16(st +            so + 8, ga0 + kk + 8);
            cp16(st +   128*40 + so,     ga1 + kk); cp16(st +   128*40 + so + 8, ga1 + kk + 8);
            cp16(st + 2*128*40 + so,     gb0 + kk); cp16(st + 2*128*40 + so + 8, gb0 + kk + 8);
            cp16(st + 3*128*40 + so,     gb1 + kk); cp16(st + 3*128*40 + so + 8, gb1 + kk + 8);
        }
        cp_commit();
    }

    int crow0 = blockIdx.y*128 + wm*32 + (lane >> 2);
    int ccol0 = bxl*128 + wn*64 + (lane & 3)*2;
#pragma unroll
    for (int mt = 0; mt < 2; mt++)
#pragma unroll
        for (int nt = 0; nt < 8; nt++) {
            float* p = Cp + (size_t)(crow0 + mt*16) * N + ccol0 + nt*8;
            *(float2*)p           = make_float2(acc[mt][nt][0], acc[mt][nt][1]);
            *(float2*)(p + 8*N)   = make_float2(acc[mt][nt][2], acc[mt][nt][3]);
        }
}

// ---------------- sum split-K partials (out projection) ----------------
__global__ void add_out_kernel(float* __restrict__ out) {
    int i = blockIdx.x * 256 + threadIdx.x;
    out[i] = g_part[i] + g_part[i + S_*EMB_];
}

// ---------------- gather + RoPE -> bf16 hi/lo (sums QKV split-K partials inline) ----------------
__global__ void gather_rope_kernel() {
    int e = blockIdx.x;
    int d = threadIdx.x;
    int m = g_kvidx[e];
    int r = g_rank[e];
    int t = e >> 2;
    int dm = d & 63;
    float invf = expf(-(float)dm * (9.210340371976184f / 64.0f));
    float fr = (float)r * invf;
    float sn, cs;
    sincosf(fr, &sn, &cs);
    int   partner = (d < 64) ? d + 64 : d - 64;
    float sgn     = (d < 64) ? -1.f : 1.f;
    int ro = m * E_ + r;
    const float scale = 0.08838834764831845f;
    const float* kb  = g_yk + t * (M_ * D_) + m * D_;
    const float* kb2 = kb + S_*M_*D_;
    float kvv = (kb[d] + kb2[d]) * cs + sgn * (kb[partner] + kb2[partner]) * sn;
    splitf(kvv, g_kh[ro*D_ + d], g_kl[ro*D_ + d]);
    int vo = t*(M_*D_) + m*D_ + d;
    float vv = g_yv[vo] + g_yv[vo + S_*M_*D_];
    splitf(vv, g_vth[(m*D_ + d)*E_ + r], g_vtl[(m*D_ + d)*E_ + r]);
#pragma unroll
    for (int h = 0; h < QH_; h++) {
        const float* qb  = g_yq + t * (M_*QH_*D_) + (m*QH_ + h) * D_;
        const float* qb2 = qb + S_*M_*QH_*D_;
        float qv = ((qb[d] + qb2[d]) * cs + sgn * (qb[partner] + qb2[partner]) * sn) * scale;
        splitf(qv, g_qh[(ro*QH_ + h)*D_ + d], g_ql[(ro*QH_ + h)*D_ + d]);
    }
}

// ---------------- split-KV tensor-core flash attention ----------------
#define AQH0 0
#define AQL0 8704
#define AKH0 17408
#define AKL0 26112
#define AVH0 34816
#define AVL0 44032
#define ATTN_SMEM_BYTES (53248*2)

__global__ __launch_bounds__(128) void attn_kernel() {
    int m  = blockIdx.z;
    int h  = blockIdx.y >> 1;
    int sp = blockIdx.y & 1;
    int L  = g_counts[m];
    int q0 = blockIdx.x * 64;
    if (q0 >= L) return;

    // KV range for this split (64-aligned midpoint)
    int kvmid = ((L + 1) / 2 + 63) & ~63;
    int kv0 = sp ? kvmid : 0;
    int kv1 = sp ? L : (kvmid < L ? kvmid : L);

    extern __shared__ bf16 as[];
    int tid = threadIdx.x, lane = tid & 31, wm = tid >> 5;

    int g   = lane >> 3;
    int lr  = (lane & 7) + ((g & 1) << 3);
    int lcA = (g >> 1) << 3;
    int brn = (lane & 7) + ((g >> 1) << 3);
    int lcB = (g & 1) << 3;
    int cb  = (lane & 3) * 2;

    for (int idx = tid; idx < 64*16; idx += 128) {
        int i = idx >> 4, dq = (idx & 15) * 8;
        size_t go = (((size_t)(m*E_ + q0 + i)*QH_ + h) << 7) + dq;
        *(uint4*)&as[AQH0 + i*136 + dq] = *(const uint4*)(g_qh + go);
        *(uint4*)&as[AQL0 + i*136 + dq] = *(const uint4*)(g_ql + go);
    }

    float Oa[16][4];
#pragma unroll
    for (int nt = 0; nt < 16; nt++)
#pragma unroll
        for (int c = 0; c < 4; c++) Oa[nt][c] = 0.f;
    float mrow[2] = {-INFINITY, -INFINITY};
    float lrow[2] = {0.f, 0.f};

    for (int kt = kv0; kt < kv1; kt += 64) {
        __syncthreads();
        for (int idx = tid; idx < 64*16; idx += 128) {
            int j = idx >> 4, dq = (idx & 15) * 8;
            size_t go = (((size_t)(m*E_ + kt + j)) << 7) + dq;
            *(uint4*)&as[AKH0 + j*136 + dq] = *(const uint4*)(g_kh + go);
            *(uint4*)&as[AKL0 + j*136 + dq] = *(const uint4*)(g_kl + go);
        }
        for (int idx = tid; idx < 128*8; idx += 128) {
            int d = idx >> 3, jq = (idx & 7) * 8;
            size_t go = ((size_t)(m*D_ + d))*E_ + kt + jq;
            *(uint4*)&as[AVH0 + d*72 + jq] = *(const uint4*)(g_vth + go);
            *(uint4*)&as[AVL0 + d*72 + jq] = *(const uint4*)(g_vtl + go);
        }
        __syncthreads();

        float Sacc[8][4];
#pragma unroll
        for (int nt = 0; nt < 8; nt++)
#pragma unroll
            for (int c = 0; c < 4; c++) Sacc[nt][c] = 0.f;
#pragma unroll
        for (int kc = 0; kc < 8; kc++) {
            uint32_t qh[4], ql[4], bh[4][4], bl[4][4];
            ldsm4(qh, &as[AQH0 + (wm*16 + lr)*136 + kc*16 + lcA]);
            ldsm4(ql, &as[AQL0 + (wm*16 + lr)*136 + kc*16 + lcA]);
#pragma unroll
            for (int nt2 = 0; nt2 < 4; nt2++) {
                ldsm4(bh[nt2], &as[AKH0 + (nt2*16 + brn)*136 + kc*16 + lcB]);
                ldsm4(bl[nt2], &as[AKL0 + (nt2*16 + brn)*136 + kc*16 + lcB]);
            }
#pragma unroll
            for (int nt2 = 0; nt2 < 4; nt2++) {
                mma16816(Sacc[2*nt2],   qh, bh[nt2][0], bh[nt2][1]);
                mma16816(Sacc[2*nt2+1], qh, bh[nt2][2], bh[nt2][3]);
            }
#pragma unroll
            for (int nt2 = 0; nt2 < 4; nt2++) {
                mma16816(Sacc[2*nt2],   qh, bl[nt2][0], bl[nt2][1]);
                mma16816(Sacc[2*nt2+1], qh, bl[nt2][2], bl[nt2][3]);
            }
#pragma unroll
            for (int nt2 = 0; nt2 < 4; nt2++) {
                mma16816(Sacc[2*nt2],   ql, bh[nt2][0], bh[nt2][1]);
                mma16816(Sacc[2*nt2+1], ql, bh[nt2][2], bh[nt2][3]);
            }
        }

        int lim = kv1 - kt;
#pragma unroll
        for (int nt = 0; nt < 8; nt++) {
            int c0 = nt*8 + cb;
            if (c0     >= lim) { Sacc[nt][0] = -1e30f; Sacc[nt][2] = -1e30f; }
            if (c0 + 1 >= lim) { Sacc[nt][1] = -1e30f; Sacc[nt][3] = -1e30f; }
        }
#pragma unroll
        for (int rr = 0; rr < 2; rr++) {
            float mx = -INFINITY;
#pragma unroll
            for (int nt = 0; nt < 8; nt++)
                mx = fmaxf(mx, fmaxf(Sacc[nt][rr*2], Sacc[nt][rr*2+1]));
            mx = fmaxf(mx, __shfl_xor_sync(0xffffffffu, mx, 1));
            mx = fmaxf(mx, __shfl_xor_sync(0xffffffffu, mx, 2));
            float mn = fmaxf(mrow[rr], mx);
            float corr = __expf(mrow[rr] - mn);
            mrow[rr] = mn;
            float ps = 0.f;
#pragma unroll
            for (int nt = 0; nt < 8; nt++) {
                float p0 = __expf(Sacc[nt][rr*2]   - mn);
                float p1 = __expf(Sacc[nt][rr*2+1] - mn);
                Sacc[nt][rr*2] = p0; Sacc[nt][rr*2+1] = p1;
                ps += p0 + p1;
            }
            ps += __shfl_xor_sync(0xffffffffu, ps, 1);
            ps += __shfl_xor_sync(0xffffffffu, ps, 2);
            lrow[rr] = lrow[rr] * corr + ps;
#pragma unroll
            for (int nt = 0; nt < 16; nt++) {
                Oa[nt][rr*2]   *= corr;
                Oa[nt][rr*2+1] *= corr;
            }
        }

#pragma unroll
        for (int kc2 = 0; kc2 < 4; kc2++) {
            uint32_t pah[4], pal[4];
            packhl(Sacc[2*kc2][0],   Sacc[2*kc2][1],   pah[0], pal[0]);
            packhl(Sacc[2*kc2][2],   Sacc[2*kc2][3],   pah[1], pal[1]);
            packhl(Sacc[2*kc2+1][0], Sacc[2*kc2+1][1], pah[2], pal[2]);
            packhl(Sacc[2*kc2+1][2], Sacc[2*kc2+1][3], pah[3], pal[3]);
#pragma unroll
            for (int nt2 = 0; nt2 < 8; nt2++) {
                uint32_t vh[4], vl[4];
                ldsm4(vh, &as[AVH0 + (nt2*16 + brn)*72 + kc2*16 + lcB]);
                ldsm4(vl, &as[AVL0 + (nt2*16 + brn)*72 + kc2*16 + lcB]);
                mma16816(Oa[2*nt2],   pah, vh[0], vh[1]);
                mma16816(Oa[2*nt2+1], pah, vh[2], vh[3]);
                mma16816(Oa[2*nt2],   pah, vl[0], vl[1]);
                mma16816(Oa[2*nt2+1], pah, vl[2], vl[3]);
                mma16816(Oa[2*nt2],   pal, vh[0], vh[1]);
                mma16816(Oa[2*nt2+1], pal, vh[2], vh[3]);
            }
        }
    }

    // write unnormalized partials (O, m, l) per row
#pragma unroll
    for (int rr = 0; rr < 2; rr++) {
        int row_local = wm*16 + (lane >> 2) + 8*rr;
        int gr = q0 + row_local;
        if (gr < L) {
            int idx = (m*E_ + gr)*QH_ + h;
            float* po = g_pO[sp][idx];
#pragma unroll
            for (int nt = 0; nt < 16; nt++) {
                int col = nt*8 + cb;
                *(float2*)(po + col) = make_float2(Oa[nt][rr*2], Oa[nt][rr*2+1]);
            }
            if (cb == 0) {
                g_pm[sp][idx] = mrow[rr];
                g_pl[sp][idx] = lrow[rr];
            }
        }
    }
}

// ---------------- combine split-KV partials + apply kv_weight, scatter ----------------
__global__ void combine_kernel() {
    int e = blockIdx.x, h = blockIdx.y;
    int d = threadIdx.x;
    int t = e >> 2, a = e & 3;
    int m = g_kvidx[e];
    int r = g_rank[e];
    int idx = (m*E_ + r)*QH_ + h;
    float m0 = g_pm[0][idx], m1 = g_pm[1][idx];
    float l0 = g_pl[0][idx], l1 = g_pl[1][idx];
    float Mx = fmaxf(m0, m1);
    float c0 = __expf(m0 - Mx), c1 = __expf(m1 - Mx);
    float l = l0*c0 + l1*c1;
    float w = g_kvw[e] / l;
    float o = (g_pO[0][idx][d]*c0 + g_pO[1][idx][d]*c1) * w;
    size_t base = (size_t)t*(A_*QH_*D_) + (a*QH_ + h)*D_ + d;
    bf16 hi = __float2bfloat16(o);
    g_aoh[base] = hi;
    g_aol[base] = __float2bfloat16(o - __bfloat162float(hi));
}

// ---------------- launch ----------------
extern "C" void kernel_launch(void* const* d_in, const int* in_sizes, int n_in,
                              void* d_out, int out_size)
{
    const float* x  = (const float*)d_in[0];
    const float* wq = (const float*)d_in[1];
    const float* wk = (const float*)d_in[2];
    const float* wv = (const float*)d_in[3];
    const float* wr = (const float*)d_in[4];
    const float* wo = (const float*)d_in[5];
    float* out = (float*)d_out;

    float *yq, *yk, *yv, *part;
    bf16 *xh, *xl, *wqh, *wql, *wkh, *wkl, *wvh, *wvl, *woh, *wol, *aoh, *aol;
    cudaGetSymbolAddress((void**)&yq, g_yq);
    cudaGetSymbolAddress((void**)&yk, g_yk);
    cudaGetSymbolAddress((void**)&yv, g_yv);
    cudaGetSymbolAddress((void**)&part, g_part);
    cudaGetSymbolAddress((void**)&xh,  g_xh);  cudaGetSymbolAddress((void**)&xl,  g_xl);
    cudaGetSymbolAddress((void**)&wqh, g_wqh); cudaGetSymbolAddress((void**)&wql, g_wql);
    cudaGetSymbolAddress((void**)&wkh, g_wkh); cudaGetSymbolAddress((void**)&wkl, g_wkl);
    cudaGetSymbolAddress((void**)&wvh, g_wvh); cudaGetSymbolAddress((void**)&wvl, g_wvl);
    cudaGetSymbolAddress((void**)&woh, g_woh); cudaGetSymbolAddress((void**)&wol, g_wol);
    cudaGetSymbolAddress((void**)&aoh, g_aoh); cudaGetSymbolAddress((void**)&aol, g_aol);

    cudaFuncSetAttribute(gemm3seg,    cudaFuncAttributeMaxDynamicSharedMemorySize, 2*GST*2);
    cudaFuncSetAttribute(attn_kernel, cudaFuncAttributeMaxDynamicSharedMemorySize, ATTN_SMEM_BYTES);

    cvt_all_kernel<<<5120, 256>>>(x, wq, wk, wv, wo);
    router_kernel<<<S_/4, 128>>>(x, wr);
    build_lists_kernel<<<1, 192>>>();
    aux_final_kernel<<<1, 256>>>(out, out_size);

    // fused Q/K/V projections, split-K=2
    gemm3seg<<<dim3(24, 8, 2), 256, 2*GST*2>>>(
        xh, xl, wqh, wql, wkh, wkl, wvh, wvl, yq, yk, yv,
        EMB_, 12, 6, M_*QH_*D_, M_*D_, M_*D_);

    gather_rope_kernel<<<E_, 128>>>();

    // split-KV attention + merge
    attn_kernel<<<dim3(E_/64, QH_*2, M_), 128, ATTN_SMEM_BYTES>>>();
    combine_kernel<<<dim3(E_, QH_), 128>>>();

    // output projection, split-K=2
    gemm3seg<<<dim3(8, 8, 2), 256, 2*GST*2>>>(
        aoh, aol, woh, wol, nullptr, nullptr, nullptr, nullptr, part, nullptr, nullptr,
        EMB_, 8, 0, EMB_, 0, 0);
    add_out_kernel<<<S_*EMB_/256, 256>>>(out);
}